// round 5
// baseline (speedup 1.0000x reference)
#include <cuda_runtime.h>
#include <cuda_fp16.h>
#include <math.h>

#define NN 50000
#define EPS_BN 1e-5f

// ---------------- scratch (device globals: allocation-free) ----------------
static __device__ __half g_h1h[(long long)NN * 256];   // fp16 h1 for gather
static __device__ float g_out1[(long long)NN * 256];   // elu(bn(gat1)), fp32 (gemm2 A)
static __device__ __half g_h2h[(long long)NN * 128];   // fp16 h2 for gather
static __device__ float g_s1[NN * 4];
static __device__ float g_d1[NN * 4];
static __device__ float g_s2[NN * 4];
static __device__ float g_d2[NN * 4];
static __device__ int g_deg[NN];
static __device__ int g_cur[NN];
static __device__ int g_rowptr[NN + 1];
static __device__ int g_pflag[64];    // lookback: 0 = not ready, else aggregate+1
static __device__ int g_col[900000];
static __device__ int g_is64;

__device__ __forceinline__ float lrelu(float x) { return x > 0.f ? x : 0.2f * x; }

// ---------------- init: zero counters + flags + edge dtype detect ----------
__global__ void __launch_bounds__(256) init_kernel(const int* __restrict__ e) {
    int i = blockIdx.x * 256 + threadIdx.x;
    if (i < NN) { g_deg[i] = 0; g_cur[i] = 0; }
    if (i < 64) g_pflag[i] = 0;
    __shared__ int bad;
    if (blockIdx.x == 0) {
        if (threadIdx.x == 0) bad = 0;
        __syncthreads();
        if (e[2 * threadIdx.x + 1] != 0) bad = 1;
        __syncthreads();
        if (threadIdx.x == 0) g_is64 = bad ? 0 : 1;
    }
}

__device__ __forceinline__ int eval_idx(const void* e, long long idx) {
    return g_is64 ? (int)((const long long*)e)[idx] : ((const int*)e)[idx];
}

__global__ void count_kernel(const void* __restrict__ e, int E, int EP) {
    int i = blockIdx.x * blockDim.x + threadIdx.x;
    if (i >= EP) return;
    int d = (i < E) ? eval_idx(e, (long long)E + i) : (i - E);
    atomicAdd(&g_deg[d], 1);
}

// ---------------- single-pass scan with parallel lookback ----------------
__global__ void __launch_bounds__(1024) scan_kernel() {
    __shared__ int sh[1024];
    __shared__ int s_prefix;
    int b = blockIdx.x;
    int t = threadIdx.x;
    int i = b * 1024 + t;
    int v = (i < NN) ? g_deg[i] : 0;
    sh[t] = v;
    __syncthreads();
#pragma unroll
    for (int off = 1; off < 1024; off <<= 1) {
        int tv = (t >= off) ? sh[t - off] : 0;
        __syncthreads();
        sh[t] += tv;
        __syncthreads();
    }
    int total = sh[1023];
    // publish aggregate (+1 as ready flag)
    if (t == 1023) {
        __threadfence();
        atomicExch(&g_pflag[b], total + 1);
    }
    // warp 0: lookback over predecessors
    if (t < 32) {
        int sum = 0;
        for (int p = t; p < b; p += 32) {
            int w;
            do { w = atomicAdd(&g_pflag[p], 0); } while (w == 0);
            sum += w - 1;
        }
#pragma unroll
        for (int off = 16; off; off >>= 1) sum += __shfl_xor_sync(0xffffffffu, sum, off);
        if (t == 0) s_prefix = sum;
    }
    __syncthreads();
    int prefix = s_prefix;
    if (i < NN) g_rowptr[i] = prefix + sh[t] - v;
    if (b == (int)gridDim.x - 1 && t == 1023) g_rowptr[NN] = prefix + total;
}

__global__ void scatter_kernel(const void* __restrict__ e, int E, int EP) {
    int i = blockIdx.x * blockDim.x + threadIdx.x;
    if (i >= EP) return;
    int s, d;
    if (i < E) { s = eval_idx(e, i); d = eval_idx(e, (long long)E + i); }
    else       { s = i - E; d = s; }
    int pos = atomicAdd(&g_cur[d], 1);
    g_col[g_rowptr[d] + pos] = s;
}

// ---------------- SGEMM + fused attention projections ----------------
// C[M,Nc] = A[M,K] @ B[K,Nc]; writes fp16 Ch; epilogue computes per-node
// s = h.a_src, d = h.a_dst per head (channels-per-head = Nc/4 = 1<<cpl2),
// reduced in smem, stored to sOut/dOut (4 floats per node).
__global__ void __launch_bounds__(256) gemm_kernel(
    const float* __restrict__ A, const float* __restrict__ B,
    __half* __restrict__ Ch,
    const float* __restrict__ as, const float* __restrict__ ad,
    float* __restrict__ sOut, float* __restrict__ dOut,
    int M, int K, int Nc, int cpl2)
{
    __shared__ float As[2][16][132];
    __shared__ float Bs[2][16][132];
    __shared__ float sm_s[128][4];
    __shared__ float sm_d[128][4];
    int tid = threadIdx.x;
    int tx = tid & 15, ty = tid >> 4;
    int row0 = blockIdx.y * 128;
    int col0 = blockIdx.x * 128;

    for (int q = tid; q < 128 * 4; q += 256) {
        ((float*)sm_s)[q] = 0.f;
        ((float*)sm_d)[q] = 0.f;
    }

    unsigned long long accp[8][4];
#pragma unroll
    for (int i = 0; i < 8; i++)
#pragma unroll
        for (int j = 0; j < 4; j++) accp[i][j] = 0ull;

    float4 pa[2], pb[2];
    {
#pragma unroll
        for (int s0 = 0; s0 < 2; s0++) {
            int slot = tid + s0 * 256;
            int r = slot >> 2;
            int kk = (slot & 3) << 2;
            float4 v = make_float4(0.f, 0.f, 0.f, 0.f);
            int gr = row0 + r;
            if (gr < M) v = *(const float4*)(A + (long long)gr * K + kk);
            pa[s0] = v;
        }
#pragma unroll
        for (int s0 = 0; s0 < 2; s0++) {
            int slot = tid + s0 * 256;
            int kk = slot >> 5;
            int c = (slot & 31) << 2;
            pb[s0] = *(const float4*)(B + (long long)kk * Nc + col0 + c);
        }
    }
    int nchunk = K >> 4;
    int buf = 0;
#pragma unroll
    for (int s0 = 0; s0 < 2; s0++) {
        int slot = tid + s0 * 256;
        int r = slot >> 2;
        int kk = (slot & 3) << 2;
        As[0][kk + 0][r] = pa[s0].x; As[0][kk + 1][r] = pa[s0].y;
        As[0][kk + 2][r] = pa[s0].z; As[0][kk + 3][r] = pa[s0].w;
        int kkb = slot >> 5;
        int c = (slot & 31) << 2;
        *(float4*)&Bs[0][kkb][c] = pb[s0];
    }
    __syncthreads();

    for (int ch = 0; ch < nchunk; ch++) {
        if (ch + 1 < nchunk) {
            int k0 = (ch + 1) << 4;
#pragma unroll
            for (int s0 = 0; s0 < 2; s0++) {
                int slot = tid + s0 * 256;
                int r = slot >> 2;
                int kk = (slot & 3) << 2;
                float4 v = make_float4(0.f, 0.f, 0.f, 0.f);
                int gr = row0 + r;
                if (gr < M) v = *(const float4*)(A + (long long)gr * K + k0 + kk);
                pa[s0] = v;
            }
#pragma unroll
            for (int s0 = 0; s0 < 2; s0++) {
                int slot = tid + s0 * 256;
                int kk = slot >> 5;
                int c = (slot & 31) << 2;
                pb[s0] = *(const float4*)(B + (long long)(k0 + kk) * Nc + col0 + c);
            }
        }
#pragma unroll
        for (int kk = 0; kk < 16; kk++) {
            float ra[8];
            *(float4*)&ra[0] = *(const float4*)&As[buf][kk][ty * 8];
            *(float4*)&ra[4] = *(const float4*)&As[buf][kk][ty * 8 + 4];
            const unsigned long long* bp = (const unsigned long long*)&Bs[buf][kk][tx * 8];
            unsigned long long rb0 = bp[0], rb1 = bp[1], rb2 = bp[2], rb3 = bp[3];
#pragma unroll
            for (int i = 0; i < 8; i++) {
                unsigned int au = __float_as_uint(ra[i]);
                unsigned long long rap;
                asm("mov.b64 %0, {%1, %1};" : "=l"(rap) : "r"(au));
                asm("fma.rn.f32x2 %0, %1, %2, %0;" : "+l"(accp[i][0]) : "l"(rap), "l"(rb0));
                asm("fma.rn.f32x2 %0, %1, %2, %0;" : "+l"(accp[i][1]) : "l"(rap), "l"(rb1));
                asm("fma.rn.f32x2 %0, %1, %2, %0;" : "+l"(accp[i][2]) : "l"(rap), "l"(rb2));
                asm("fma.rn.f32x2 %0, %1, %2, %0;" : "+l"(accp[i][3]) : "l"(rap), "l"(rb3));
            }
        }
        if (ch + 1 < nchunk) {
            int nb = buf ^ 1;
#pragma unroll
            for (int s0 = 0; s0 < 2; s0++) {
                int slot = tid + s0 * 256;
                int r = slot >> 2;
                int kk = (slot & 3) << 2;
                As[nb][kk + 0][r] = pa[s0].x; As[nb][kk + 1][r] = pa[s0].y;
                As[nb][kk + 2][r] = pa[s0].z; As[nb][kk + 3][r] = pa[s0].w;
                int kkb = slot >> 5;
                int c = (slot & 31) << 2;
                *(float4*)&Bs[nb][kkb][c] = pb[s0];
            }
            __syncthreads();
            buf = nb;
        }
    }

    // epilogue: fp16 store + fused s/d projection
    int cg = col0 + tx * 8;                 // global channel of this thread's 8 cols
    int hl = (tx * 8) >> cpl2;              // local head index within this block
    float4 av0 = *(const float4*)(as + cg);
    float4 av1 = *(const float4*)(as + cg + 4);
    float4 dv0 = *(const float4*)(ad + cg);
    float4 dv1 = *(const float4*)(ad + cg + 4);
#pragma unroll
    for (int i = 0; i < 8; i++) {
        int gr = row0 + ty * 8 + i;
        if (gr < M) {
            float o[8];
#pragma unroll
            for (int j = 0; j < 4; j++) {
                unsigned int lo, hi;
                asm("mov.b64 {%0, %1}, %2;" : "=r"(lo), "=r"(hi) : "l"(accp[i][j]));
                o[2 * j]     = __uint_as_float(lo);
                o[2 * j + 1] = __uint_as_float(hi);
            }
            uint4 w;
            __half2 p0 = __float22half2_rn(make_float2(o[0], o[1]));
            __half2 p1 = __float22half2_rn(make_float2(o[2], o[3]));
            __half2 p2 = __float22half2_rn(make_float2(o[4], o[5]));
            __half2 p3 = __float22half2_rn(make_float2(o[6], o[7]));
            w.x = *(unsigned int*)&p0; w.y = *(unsigned int*)&p1;
            w.z = *(unsigned int*)&p2; w.w = *(unsigned int*)&p3;
            *(uint4*)(Ch + (long long)gr * Nc + cg) = w;

            float ps = o[0]*av0.x + o[1]*av0.y + o[2]*av0.z + o[3]*av0.w
                     + o[4]*av1.x + o[5]*av1.y + o[6]*av1.z + o[7]*av1.w;
            float pd = o[0]*dv0.x + o[1]*dv0.y + o[2]*dv0.z + o[3]*dv0.w
                     + o[4]*dv1.x + o[5]*dv1.y + o[6]*dv1.z + o[7]*dv1.w;
            atomicAdd(&sm_s[ty * 8 + i][hl], ps);
            atomicAdd(&sm_d[ty * 8 + i][hl], pd);
        }
    }
    __syncthreads();
    int hpb = 128 >> cpl2;                  // heads covered by this col-block
    int hb  = col0 >> cpl2;                 // first global head in this block
    for (int q = tid; q < 128 * hpb; q += 256) {
        int r = q / hpb, hh = q % hpb;
        int gr = row0 + r;
        if (gr < M) {
            sOut[4 * gr + hb + hh] = sm_s[r][hh];
            dOut[4 * gr + hb + hh] = sm_d[r][hh];
        }
    }
}

__device__ __forceinline__ void acc8_fp16(float* acc, uint4 v, float ex) {
    float2 f0 = __half22float2(*(__half2*)&v.x);
    float2 f1 = __half22float2(*(__half2*)&v.y);
    float2 f2 = __half22float2(*(__half2*)&v.z);
    float2 f3 = __half22float2(*(__half2*)&v.w);
    acc[0] += ex * f0.x; acc[1] += ex * f0.y;
    acc[2] += ex * f1.x; acc[3] += ex * f1.y;
    acc[4] += ex * f2.x; acc[5] += ex * f2.y;
    acc[6] += ex * f3.x; acc[7] += ex * f3.y;
}

// ---------------- GAT aggregation layer 1 (fp16 gather, fused BN+ELU) --------
__global__ void __launch_bounds__(256) agg1_kernel(
    const float* __restrict__ b1, const float* __restrict__ gm,
    const float* __restrict__ bt, const float* __restrict__ mn,
    const float* __restrict__ vr)
{
    int gw = (blockIdx.x * blockDim.x + threadIdx.x) >> 5;
    if (gw >= NN) return;
    int l = threadIdx.x & 31;
    int start = g_rowptr[gw], end = g_rowptr[gw + 1];
    int head = l >> 3;
    float dh = g_d1[4 * gw + head];
    int c0 = l << 3;
    float acc[8] = {0.f, 0.f, 0.f, 0.f, 0.f, 0.f, 0.f, 0.f};
    float den = 0.f;

    int j = start;
    for (; j + 4 <= end; j += 4) {
        int s0 = g_col[j], s1 = g_col[j + 1], s2 = g_col[j + 2], s3 = g_col[j + 3];
        float e0 = __expf(lrelu(g_s1[4 * s0 + head] + dh));
        float e1 = __expf(lrelu(g_s1[4 * s1 + head] + dh));
        float e2 = __expf(lrelu(g_s1[4 * s2 + head] + dh));
        float e3 = __expf(lrelu(g_s1[4 * s3 + head] + dh));
        uint4 v0 = *(const uint4*)(g_h1h + (long long)s0 * 256 + c0);
        uint4 v1 = *(const uint4*)(g_h1h + (long long)s1 * 256 + c0);
        uint4 v2 = *(const uint4*)(g_h1h + (long long)s2 * 256 + c0);
        uint4 v3 = *(const uint4*)(g_h1h + (long long)s3 * 256 + c0);
        den += (e0 + e1) + (e2 + e3);
        acc8_fp16(acc, v0, e0);
        acc8_fp16(acc, v1, e1);
        acc8_fp16(acc, v2, e2);
        acc8_fp16(acc, v3, e3);
    }
    for (; j < end; j++) {
        int s = g_col[j];
        float ex = __expf(lrelu(g_s1[4 * s + head] + dh));
        den += ex;
        uint4 v = *(const uint4*)(g_h1h + (long long)s * 256 + c0);
        acc8_fp16(acc, v, ex);
    }
    float inv = 1.f / (den + 1e-16f);
    float out[8];
#pragma unroll
    for (int i = 0; i < 8; i++) {
        int c = c0 + i;
        float v = acc[i] * inv + b1[c];
        v = (v - mn[c]) * rsqrtf(vr[c] + EPS_BN) * gm[c] + bt[c];
        out[i] = v > 0.f ? v : expm1f(v);
    }
    float4* op = (float4*)(g_out1 + (long long)gw * 256 + c0);
    op[0] = make_float4(out[0], out[1], out[2], out[3]);
    op[1] = make_float4(out[4], out[5], out[6], out[7]);
}

// ------------ GAT aggregation layer 2 (fp16 gather, BN+ELU+FC head) ----------
__global__ void __launch_bounds__(256) agg2_kernel(
    const float* __restrict__ b2, const float* __restrict__ gm,
    const float* __restrict__ bt, const float* __restrict__ mn,
    const float* __restrict__ vr, const float* __restrict__ fcW,
    const float* __restrict__ fcb, float* __restrict__ out)
{
    int gw = (blockIdx.x * blockDim.x + threadIdx.x) >> 5;
    if (gw >= NN) return;
    int l = threadIdx.x & 31;
    int start = g_rowptr[gw], end = g_rowptr[gw + 1];
    int head = l >> 3;
    float dh = g_d2[4 * gw + head];
    int c0 = l << 2;
    float acc[4] = {0.f, 0.f, 0.f, 0.f};
    float den = 0.f;

    int j = start;
    for (; j + 4 <= end; j += 4) {
        int s0 = g_col[j], s1 = g_col[j + 1], s2 = g_col[j + 2], s3 = g_col[j + 3];
        float e0 = __expf(lrelu(g_s2[4 * s0 + head] + dh));
        float e1 = __expf(lrelu(g_s2[4 * s1 + head] + dh));
        float e2 = __expf(lrelu(g_s2[4 * s2 + head] + dh));
        float e3 = __expf(lrelu(g_s2[4 * s3 + head] + dh));
        uint2 v0 = *(const uint2*)(g_h2h + (long long)s0 * 128 + c0);
        uint2 v1 = *(const uint2*)(g_h2h + (long long)s1 * 128 + c0);
        uint2 v2 = *(const uint2*)(g_h2h + (long long)s2 * 128 + c0);
        uint2 v3 = *(const uint2*)(g_h2h + (long long)s3 * 128 + c0);
        den += (e0 + e1) + (e2 + e3);
        float2 f;
        f = __half22float2(*(__half2*)&v0.x); acc[0] += e0*f.x; acc[1] += e0*f.y;
        f = __half22float2(*(__half2*)&v0.y); acc[2] += e0*f.x; acc[3] += e0*f.y;
        f = __half22float2(*(__half2*)&v1.x); acc[0] += e1*f.x; acc[1] += e1*f.y;
        f = __half22float2(*(__half2*)&v1.y); acc[2] += e1*f.x; acc[3] += e1*f.y;
        f = __half22float2(*(__half2*)&v2.x); acc[0] += e2*f.x; acc[1] += e2*f.y;
        f = __half22float2(*(__half2*)&v2.y); acc[2] += e2*f.x; acc[3] += e2*f.y;
        f = __half22float2(*(__half2*)&v3.x); acc[0] += e3*f.x; acc[1] += e3*f.y;
        f = __half22float2(*(__half2*)&v3.y); acc[2] += e3*f.x; acc[3] += e3*f.y;
    }
    for (; j < end; j++) {
        int s = g_col[j];
        float ex = __expf(lrelu(g_s2[4 * s + head] + dh));
        den += ex;
        uint2 v0 = *(const uint2*)(g_h2h + (long long)s * 128 + c0);
        float2 f;
        f = __half22float2(*(__half2*)&v0.x); acc[0] += ex*f.x; acc[1] += ex*f.y;
        f = __half22float2(*(__half2*)&v0.y); acc[2] += ex*f.x; acc[3] += ex*f.y;
    }
    float inv = 1.f / (den + 1e-16f);
    float r = 0.f;
#pragma unroll
    for (int i = 0; i < 4; i++) {
        int c = c0 + i;
        float v = acc[i] * inv + b2[c];
        v = (v - mn[c]) * rsqrtf(vr[c] + EPS_BN) * gm[c] + bt[c];
        v = v > 0.f ? v : expm1f(v);
        r += v * fcW[c];
    }
#pragma unroll
    for (int off = 16; off; off >>= 1) r += __shfl_xor_sync(0xffffffffu, r, off);
    if (l == 0) out[gw] = r + fcb[0];
}

// ---------------- launch ----------------
extern "C" void kernel_launch(void* const* d_in, const int* in_sizes, int n_in,
                              void* d_out, int out_size) {
    const float* x    = (const float*)d_in[0];
    const void*  eidx = d_in[1];
    const float* W1   = (const float*)d_in[2];
    const float* a1s  = (const float*)d_in[3];
    const float* a1d  = (const float*)d_in[4];
    const float* b1   = (const float*)d_in[5];
    const float* g1   = (const float*)d_in[6];
    const float* be1  = (const float*)d_in[7];
    const float* m1   = (const float*)d_in[8];
    const float* v1   = (const float*)d_in[9];
    const float* W2   = (const float*)d_in[10];
    const float* a2s  = (const float*)d_in[11];
    const float* a2d  = (const float*)d_in[12];
    const float* b2   = (const float*)d_in[13];
    const float* g2   = (const float*)d_in[14];
    const float* be2  = (const float*)d_in[15];
    const float* m2   = (const float*)d_in[16];
    const float* v2   = (const float*)d_in[17];
    const float* fcW  = (const float*)d_in[18];
    const float* fcb  = (const float*)d_in[19];

    int E  = in_sizes[1] / 2;
    int EP = E + NN;

    float *out1p, *s1p, *d1p, *s2p, *d2p;
    __half *h1hp, *h2hp;
    cudaGetSymbolAddress((void**)&out1p, g_out1);
    cudaGetSymbolAddress((void**)&h1hp,  g_h1h);
    cudaGetSymbolAddress((void**)&h2hp,  g_h2h);
    cudaGetSymbolAddress((void**)&s1p,   g_s1);
    cudaGetSymbolAddress((void**)&d1p,   g_d1);
    cudaGetSymbolAddress((void**)&s2p,   g_s2);
    cudaGetSymbolAddress((void**)&d2p,   g_d2);

    const int TPB = 256;
    int warp_blocks = (NN * 32 + TPB - 1) / TPB;
    int scan_blocks = (NN + 1023) / 1024;          // 49

    init_kernel<<<(NN + 255) / 256, 256>>>((const int*)eidx);              // 1
    count_kernel<<<(EP + TPB - 1) / TPB, TPB>>>(eidx, E, EP);              // 2
    scan_kernel<<<scan_blocks, 1024>>>();                                  // 3
    scatter_kernel<<<(EP + TPB - 1) / TPB, TPB>>>(eidx, E, EP);            // 4

    // Layer 1 (gemm+sd fused)                                             // 5
    gemm_kernel<<<dim3(2, (NN + 127) / 128), 256>>>(
        x, W1, h1hp, a1s, a1d, s1p, d1p, NN, 128, 256, 6);
    agg1_kernel<<<warp_blocks, TPB>>>(b1, g1, be1, m1, v1);                // 6 <- profiled

    // Layer 2                                                             // 7
    gemm_kernel<<<dim3(1, (NN + 127) / 128), 256>>>(
        out1p, W2, h2hp, a2s, a2d, s2p, d2p, NN, 256, 128, 5);
    agg2_kernel<<<warp_blocks, TPB>>>(b2, g2, be2, m2, v2, fcW, fcb, (float*)d_out); // 8
}

// round 6
// speedup vs baseline: 1.0662x; 1.0662x over previous
#include <cuda_runtime.h>
#include <cuda_fp16.h>
#include <math.h>

#define NN 50000
#define EPS_BN 1e-5f

// ---------------- scratch (device globals: allocation-free) ----------------
static __device__ __half g_h1h[(long long)NN * 256];   // fp16 h1 for gather
static __device__ float g_out1[(long long)NN * 256];   // elu(bn(gat1)), fp32 (gemm2 A)
static __device__ __half g_h2h[(long long)NN * 128];   // fp16 h2 for gather
static __device__ float g_s1[NN * 4];
static __device__ float g_d1[NN * 4];
static __device__ float g_s2[NN * 4];
static __device__ float g_d2[NN * 4];
static __device__ int g_deg[NN];
static __device__ int g_cur[NN];
static __device__ int g_rowptr[NN + 1];
static __device__ int g_pflag[64];
static __device__ int g_col[900000];
static __device__ int g_is64;

__device__ __forceinline__ float lrelu(float x) { return x > 0.f ? x : 0.2f * x; }

// ---------------- init + edge dtype detect ----------------
__global__ void __launch_bounds__(256) init_kernel(const int* __restrict__ e) {
    int i = blockIdx.x * 256 + threadIdx.x;
    if (i < NN) { g_deg[i] = 0; g_cur[i] = 0; }
    if (i < 64) g_pflag[i] = 0;
    __shared__ int bad;
    if (blockIdx.x == 0) {
        if (threadIdx.x == 0) bad = 0;
        __syncthreads();
        if (e[2 * threadIdx.x + 1] != 0) bad = 1;
        __syncthreads();
        if (threadIdx.x == 0) g_is64 = bad ? 0 : 1;
    }
}

__device__ __forceinline__ int eval_idx(const void* e, long long idx) {
    return g_is64 ? (int)((const long long*)e)[idx] : ((const int*)e)[idx];
}

__global__ void count_kernel(const void* __restrict__ e, int E, int EP) {
    int i = blockIdx.x * blockDim.x + threadIdx.x;
    if (i >= EP) return;
    int d = (i < E) ? eval_idx(e, (long long)E + i) : (i - E);
    atomicAdd(&g_deg[d], 1);
}

// ---------------- single-pass scan with parallel lookback ----------------
__global__ void __launch_bounds__(1024) scan_kernel() {
    __shared__ int sh[1024];
    __shared__ int s_prefix;
    int b = blockIdx.x;
    int t = threadIdx.x;
    int i = b * 1024 + t;
    int v = (i < NN) ? g_deg[i] : 0;
    sh[t] = v;
    __syncthreads();
#pragma unroll
    for (int off = 1; off < 1024; off <<= 1) {
        int tv = (t >= off) ? sh[t - off] : 0;
        __syncthreads();
        sh[t] += tv;
        __syncthreads();
    }
    int total = sh[1023];
    if (t == 1023) {
        __threadfence();
        atomicExch(&g_pflag[b], total + 1);
    }
    if (t < 32) {
        int sum = 0;
        for (int p = t; p < b; p += 32) {
            int w;
            do { w = atomicAdd(&g_pflag[p], 0); } while (w == 0);
            sum += w - 1;
        }
#pragma unroll
        for (int off = 16; off; off >>= 1) sum += __shfl_xor_sync(0xffffffffu, sum, off);
        if (t == 0) s_prefix = sum;
    }
    __syncthreads();
    int prefix = s_prefix;
    if (i < NN) g_rowptr[i] = prefix + sh[t] - v;
    if (b == (int)gridDim.x - 1 && t == 1023) g_rowptr[NN] = prefix + total;
}

__global__ void scatter_kernel(const void* __restrict__ e, int E, int EP) {
    int i = blockIdx.x * blockDim.x + threadIdx.x;
    if (i >= EP) return;
    int s, d;
    if (i < E) { s = eval_idx(e, i); d = eval_idx(e, (long long)E + i); }
    else       { s = i - E; d = s; }
    int pos = atomicAdd(&g_cur[d], 1);
    g_col[g_rowptr[d] + pos] = s;
}

// ---------------- tf32 helpers ----------------
__device__ __forceinline__ unsigned int f2tf(float f) {
    unsigned int r;
    asm("cvt.rna.tf32.f32 %0, %1;" : "=r"(r) : "f"(f));
    return r;
}

__device__ __forceinline__ void mma_tf32(
    float* c, unsigned int a0, unsigned int a1, unsigned int a2, unsigned int a3,
    unsigned int b0, unsigned int b1)
{
    asm("mma.sync.aligned.m16n8k8.row.col.f32.tf32.tf32.f32 "
        "{%0,%1,%2,%3}, {%4,%5,%6,%7}, {%8,%9}, {%0,%1,%2,%3};"
        : "+f"(c[0]), "+f"(c[1]), "+f"(c[2]), "+f"(c[3])
        : "r"(a0), "r"(a1), "r"(a2), "r"(a3), "r"(b0), "r"(b1));
}

// ---------------- GEMM (tensor-core tf32 3x) + fused s/d projections --------
// C[M,Nc] = A[M,K] @ B[K,Nc], writes fp16 Ch, epilogue computes per-node
// per-head s = h.a_src, d = h.a_dst (channels/head = 1<<cpl2).
// 128x128 block tile, 8 warps in 2x4 grid (warp tile 64x32).
__global__ void __launch_bounds__(256) gemm_kernel(
    const float* __restrict__ A, const float* __restrict__ B,
    __half* __restrict__ Ch,
    const float* __restrict__ as, const float* __restrict__ ad,
    float* __restrict__ sOut, float* __restrict__ dOut,
    int M, int K, int Nc, int cpl2)
{
    __shared__ float As[16][132];
    __shared__ float Bs[16][132];
    __shared__ float sm_s[128][4];
    __shared__ float sm_d[128][4];
    int tid = threadIdx.x;
    int lane = tid & 31;
    int w = tid >> 5;
    int wm = (w & 1) * 64;      // warp m-offset
    int wn = (w >> 1) * 32;     // warp n-offset
    int lr = lane >> 2;         // 0..7
    int lc = lane & 3;          // 0..3
    int row0 = blockIdx.y * 128;
    int col0 = blockIdx.x * 128;

    for (int q = tid; q < 512; q += 256) {
        ((float*)sm_s)[q] = 0.f;
        ((float*)sm_d)[q] = 0.f;
    }

    float c[4][4][4];   // [mf][nf][reg]
#pragma unroll
    for (int i = 0; i < 4; i++)
#pragma unroll
        for (int j = 0; j < 4; j++)
#pragma unroll
            for (int r = 0; r < 4; r++) c[i][j][r] = 0.f;

    for (int k0 = 0; k0 < K; k0 += 16) {
        if (k0) __syncthreads();
#pragma unroll
        for (int s0 = 0; s0 < 2; s0++) {
            int slot = tid + s0 * 256;
            int r = slot >> 2;
            int kk = (slot & 3) << 2;
            float4 v = make_float4(0.f, 0.f, 0.f, 0.f);
            int gr = row0 + r;
            if (gr < M) v = *(const float4*)(A + (long long)gr * K + k0 + kk);
            As[kk + 0][r] = v.x; As[kk + 1][r] = v.y;
            As[kk + 2][r] = v.z; As[kk + 3][r] = v.w;
            int kkb = slot >> 5;
            int cc = (slot & 31) << 2;
            *(float4*)&Bs[kkb][cc] = *(const float4*)(B + (long long)(k0 + kkb) * Nc + col0 + cc);
        }
        __syncthreads();

#pragma unroll
        for (int ks = 0; ks < 16; ks += 8) {
            // B fragments (hi/lo)
            unsigned int bh[4][2], bl[4][2];
#pragma unroll
            for (int nf = 0; nf < 4; nf++) {
                int n = wn + nf * 8 + lr;
                float b0 = Bs[ks + lc][n];
                float b1 = Bs[ks + lc + 4][n];
                bh[nf][0] = f2tf(b0);
                bh[nf][1] = f2tf(b1);
                bl[nf][0] = f2tf(b0 - __uint_as_float(bh[nf][0]));
                bl[nf][1] = f2tf(b1 - __uint_as_float(bh[nf][1]));
            }
#pragma unroll
            for (int mf = 0; mf < 4; mf++) {
                int r = wm + mf * 16 + lr;
                float a0 = As[ks + lc][r];
                float a1 = As[ks + lc][r + 8];
                float a2 = As[ks + lc + 4][r];
                float a3 = As[ks + lc + 4][r + 8];
                unsigned int ah0 = f2tf(a0), ah1 = f2tf(a1), ah2 = f2tf(a2), ah3 = f2tf(a3);
                unsigned int al0 = f2tf(a0 - __uint_as_float(ah0));
                unsigned int al1 = f2tf(a1 - __uint_as_float(ah1));
                unsigned int al2 = f2tf(a2 - __uint_as_float(ah2));
                unsigned int al3 = f2tf(a3 - __uint_as_float(ah3));
#pragma unroll
                for (int nf = 0; nf < 4; nf++) {
                    mma_tf32(c[mf][nf], ah0, ah1, ah2, ah3, bh[nf][0], bh[nf][1]);
                    mma_tf32(c[mf][nf], ah0, ah1, ah2, ah3, bl[nf][0], bl[nf][1]);
                    mma_tf32(c[mf][nf], al0, al1, al2, al3, bh[nf][0], bh[nf][1]);
                }
            }
        }
    }

    // ---- epilogue: fp16 store + fused s/d (one head per warp n-tile) ----
    int hlw = wn >> cpl2;   // local head index for this warp's 32 cols
    float av[4][2], dv[4][2];
#pragma unroll
    for (int nf = 0; nf < 4; nf++) {
#pragma unroll
        for (int e = 0; e < 2; e++) {
            int cg = col0 + wn + nf * 8 + lc * 2 + e;
            av[nf][e] = as[cg];
            dv[nf][e] = ad[cg];
        }
    }
#pragma unroll
    for (int mf = 0; mf < 4; mf++) {
#pragma unroll
        for (int rs = 0; rs < 2; rs++) {
            int row = wm + mf * 16 + lr + rs * 8;
            int gr = row0 + row;
            if (gr < M) {
                float ps = 0.f, pd = 0.f;
#pragma unroll
                for (int nf = 0; nf < 4; nf++) {
                    float o0 = c[mf][nf][rs * 2 + 0];
                    float o1 = c[mf][nf][rs * 2 + 1];
                    ps += o0 * av[nf][0] + o1 * av[nf][1];
                    pd += o0 * dv[nf][0] + o1 * dv[nf][1];
                    __half2 hp = __float22half2_rn(make_float2(o0, o1));
                    *(__half2*)(Ch + (long long)gr * Nc + col0 + wn + nf * 8 + lc * 2) = hp;
                }
                atomicAdd(&sm_s[row][hlw], ps);
                atomicAdd(&sm_d[row][hlw], pd);
            }
        }
    }
    __syncthreads();
    int hpb = 128 >> cpl2;
    int hb  = col0 >> cpl2;
    for (int q = tid; q < 128 * hpb; q += 256) {
        int r = q / hpb, hh = q % hpb;
        int gr = row0 + r;
        if (gr < M) {
            sOut[4 * gr + hb + hh] = sm_s[r][hh];
            dOut[4 * gr + hb + hh] = sm_d[r][hh];
        }
    }
}

__device__ __forceinline__ void acc8_fp16(float* acc, uint4 v, float ex) {
    float2 f0 = __half22float2(*(__half2*)&v.x);
    float2 f1 = __half22float2(*(__half2*)&v.y);
    float2 f2 = __half22float2(*(__half2*)&v.z);
    float2 f3 = __half22float2(*(__half2*)&v.w);
    acc[0] += ex * f0.x; acc[1] += ex * f0.y;
    acc[2] += ex * f1.x; acc[3] += ex * f1.y;
    acc[4] += ex * f2.x; acc[5] += ex * f2.y;
    acc[6] += ex * f3.x; acc[7] += ex * f3.y;
}

// ---------------- GAT aggregation layer 1 (fp16 gather, fused BN+ELU) --------
__global__ void __launch_bounds__(256) agg1_kernel(
    const float* __restrict__ b1, const float* __restrict__ gm,
    const float* __restrict__ bt, const float* __restrict__ mn,
    const float* __restrict__ vr)
{
    int gw = (blockIdx.x * blockDim.x + threadIdx.x) >> 5;
    if (gw >= NN) return;
    int l = threadIdx.x & 31;
    int start = g_rowptr[gw], end = g_rowptr[gw + 1];
    int head = l >> 3;
    float dh = g_d1[4 * gw + head];
    int c0 = l << 3;
    float acc[8] = {0.f, 0.f, 0.f, 0.f, 0.f, 0.f, 0.f, 0.f};
    float den = 0.f;

    int j = start;
    for (; j + 4 <= end; j += 4) {
        int s0 = g_col[j], s1 = g_col[j + 1], s2 = g_col[j + 2], s3 = g_col[j + 3];
        float e0 = __expf(lrelu(g_s1[4 * s0 + head] + dh));
        float e1 = __expf(lrelu(g_s1[4 * s1 + head] + dh));
        float e2 = __expf(lrelu(g_s1[4 * s2 + head] + dh));
        float e3 = __expf(lrelu(g_s1[4 * s3 + head] + dh));
        uint4 v0 = *(const uint4*)(g_h1h + (long long)s0 * 256 + c0);
        uint4 v1 = *(const uint4*)(g_h1h + (long long)s1 * 256 + c0);
        uint4 v2 = *(const uint4*)(g_h1h + (long long)s2 * 256 + c0);
        uint4 v3 = *(const uint4*)(g_h1h + (long long)s3 * 256 + c0);
        den += (e0 + e1) + (e2 + e3);
        acc8_fp16(acc, v0, e0);
        acc8_fp16(acc, v1, e1);
        acc8_fp16(acc, v2, e2);
        acc8_fp16(acc, v3, e3);
    }
    for (; j < end; j++) {
        int s = g_col[j];
        float ex = __expf(lrelu(g_s1[4 * s + head] + dh));
        den += ex;
        uint4 v = *(const uint4*)(g_h1h + (long long)s * 256 + c0);
        acc8_fp16(acc, v, ex);
    }
    float inv = 1.f / (den + 1e-16f);
    float out[8];
#pragma unroll
    for (int i = 0; i < 8; i++) {
        int cc = c0 + i;
        float v = acc[i] * inv + b1[cc];
        v = (v - mn[cc]) * rsqrtf(vr[cc] + EPS_BN) * gm[cc] + bt[cc];
        out[i] = v > 0.f ? v : expm1f(v);
    }
    float4* op = (float4*)(g_out1 + (long long)gw * 256 + c0);
    op[0] = make_float4(out[0], out[1], out[2], out[3]);
    op[1] = make_float4(out[4], out[5], out[6], out[7]);
}

// ------------ GAT aggregation layer 2 (fp16 gather, BN+ELU+FC head) ----------
__global__ void __launch_bounds__(256) agg2_kernel(
    const float* __restrict__ b2, const float* __restrict__ gm,
    const float* __restrict__ bt, const float* __restrict__ mn,
    const float* __restrict__ vr, const float* __restrict__ fcW,
    const float* __restrict__ fcb, float* __restrict__ out)
{
    int gw = (blockIdx.x * blockDim.x + threadIdx.x) >> 5;
    if (gw >= NN) return;
    int l = threadIdx.x & 31;
    int start = g_rowptr[gw], end = g_rowptr[gw + 1];
    int head = l >> 3;
    float dh = g_d2[4 * gw + head];
    int c0 = l << 2;
    float acc[4] = {0.f, 0.f, 0.f, 0.f};
    float den = 0.f;

    int j = start;
    for (; j + 4 <= end; j += 4) {
        int s0 = g_col[j], s1 = g_col[j + 1], s2 = g_col[j + 2], s3 = g_col[j + 3];
        float e0 = __expf(lrelu(g_s2[4 * s0 + head] + dh));
        float e1 = __expf(lrelu(g_s2[4 * s1 + head] + dh));
        float e2 = __expf(lrelu(g_s2[4 * s2 + head] + dh));
        float e3 = __expf(lrelu(g_s2[4 * s3 + head] + dh));
        uint2 v0 = *(const uint2*)(g_h2h + (long long)s0 * 128 + c0);
        uint2 v1 = *(const uint2*)(g_h2h + (long long)s1 * 128 + c0);
        uint2 v2 = *(const uint2*)(g_h2h + (long long)s2 * 128 + c0);
        uint2 v3 = *(const uint2*)(g_h2h + (long long)s3 * 128 + c0);
        den += (e0 + e1) + (e2 + e3);
        float2 f;
        f = __half22float2(*(__half2*)&v0.x); acc[0] += e0*f.x; acc[1] += e0*f.y;
        f = __half22float2(*(__half2*)&v0.y); acc[2] += e0*f.x; acc[3] += e0*f.y;
        f = __half22float2(*(__half2*)&v1.x); acc[0] += e1*f.x; acc[1] += e1*f.y;
        f = __half22float2(*(__half2*)&v1.y); acc[2] += e1*f.x; acc[3] += e1*f.y;
        f = __half22float2(*(__half2*)&v2.x); acc[0] += e2*f.x; acc[1] += e2*f.y;
        f = __half22float2(*(__half2*)&v2.y); acc[2] += e2*f.x; acc[3] += e2*f.y;
        f = __half22float2(*(__half2*)&v3.x); acc[0] += e3*f.x; acc[1] += e3*f.y;
        f = __half22float2(*(__half2*)&v3.y); acc[2] += e3*f.x; acc[3] += e3*f.y;
    }
    for (; j < end; j++) {
        int s = g_col[j];
        float ex = __expf(lrelu(g_s2[4 * s + head] + dh));
        den += ex;
        uint2 v0 = *(const uint2*)(g_h2h + (long long)s * 128 + c0);
        float2 f;
        f = __half22float2(*(__half2*)&v0.x); acc[0] += ex*f.x; acc[1] += ex*f.y;
        f = __half22float2(*(__half2*)&v0.y); acc[2] += ex*f.x; acc[3] += ex*f.y;
    }
    float inv = 1.f / (den + 1e-16f);
    float r = 0.f;
#pragma unroll
    for (int i = 0; i < 4; i++) {
        int cc = c0 + i;
        float v = acc[i] * inv + b2[cc];
        v = (v - mn[cc]) * rsqrtf(vr[cc] + EPS_BN) * gm[cc] + bt[cc];
        v = v > 0.f ? v : expm1f(v);
        r += v * fcW[cc];
    }
#pragma unroll
    for (int off = 16; off; off >>= 1) r += __shfl_xor_sync(0xffffffffu, r, off);
    if (l == 0) out[gw] = r + fcb[0];
}

// ---------------- launch ----------------
extern "C" void kernel_launch(void* const* d_in, const int* in_sizes, int n_in,
                              void* d_out, int out_size) {
    const float* x    = (const float*)d_in[0];
    const void*  eidx = d_in[1];
    const float* W1   = (const float*)d_in[2];
    const float* a1s  = (const float*)d_in[3];
    const float* a1d  = (const float*)d_in[4];
    const float* b1   = (const float*)d_in[5];
    const float* g1   = (const float*)d_in[6];
    const float* be1  = (const float*)d_in[7];
    const float* m1   = (const float*)d_in[8];
    const float* v1   = (const float*)d_in[9];
    const float* W2   = (const float*)d_in[10];
    const float* a2s  = (const float*)d_in[11];
    const float* a2d  = (const float*)d_in[12];
    const float* b2   = (const float*)d_in[13];
    const float* g2   = (const float*)d_in[14];
    const float* be2  = (const float*)d_in[15];
    const float* m2   = (const float*)d_in[16];
    const float* v2   = (const float*)d_in[17];
    const float* fcW  = (const float*)d_in[18];
    const float* fcb  = (const float*)d_in[19];

    int E  = in_sizes[1] / 2;
    int EP = E + NN;

    float *out1p, *s1p, *d1p, *s2p, *d2p;
    __half *h1hp, *h2hp;
    cudaGetSymbolAddress((void**)&out1p, g_out1);
    cudaGetSymbolAddress((void**)&h1hp,  g_h1h);
    cudaGetSymbolAddress((void**)&h2hp,  g_h2h);
    cudaGetSymbolAddress((void**)&s1p,   g_s1);
    cudaGetSymbolAddress((void**)&d1p,   g_d1);
    cudaGetSymbolAddress((void**)&s2p,   g_s2);
    cudaGetSymbolAddress((void**)&d2p,   g_d2);

    const int TPB = 256;
    int warp_blocks = (NN * 32 + TPB - 1) / TPB;
    int scan_blocks = (NN + 1023) / 1024;

    init_kernel<<<(NN + 255) / 256, 256>>>((const int*)eidx);
    count_kernel<<<(EP + TPB - 1) / TPB, TPB>>>(eidx, E, EP);
    scan_kernel<<<scan_blocks, 1024>>>();
    scatter_kernel<<<(EP + TPB - 1) / TPB, TPB>>>(eidx, E, EP);

    // Layer 1 (tensor-core gemm + fused s/d)
    gemm_kernel<<<dim3(2, (NN + 127) / 128), 256>>>(
        x, W1, h1hp, a1s, a1d, s1p, d1p, NN, 128, 256, 6);
    agg1_kernel<<<warp_blocks, TPB>>>(b1, g1, be1, m1, v1);

    // Layer 2
    gemm_kernel<<<dim3(1, (NN + 127) / 128), 256>>>(
        out1p, W2, h2hp, a2s, a2d, s2p, d2p, NN, 256, 128, 5);
    agg2_kernel<<<warp_blocks, TPB>>>(b2, g2, be2, m2, v2, fcW, fcb, (float*)d_out);
}

// round 7
// speedup vs baseline: 1.5976x; 1.4984x over previous
#include <cuda_runtime.h>
#include <cuda_fp16.h>
#include <math.h>

#define NN 50000
#define EPS_BN 1e-5f

// ---------------- scratch (device globals: allocation-free) ----------------
static __device__ __half g_h1h[(long long)NN * 256];   // fp16 h1 for gather
static __device__ __half g_out1h[(long long)NN * 256]; // fp16 elu(bn(gat1)) (gemm2 A)
static __device__ __half g_h2h[(long long)NN * 128];   // fp16 h2 for gather
static __device__ float g_s1[NN * 4];
static __device__ float g_d1[NN * 4];
static __device__ float g_s2[NN * 4];
static __device__ float g_d2[NN * 4];
static __device__ int g_deg[NN];
static __device__ int g_cur[NN];
static __device__ int g_rowptr[NN + 1];
static __device__ int g_pflag[64];
static __device__ int g_col[900000];
static __device__ int g_is64;

__device__ __forceinline__ float lrelu(float x) { return x > 0.f ? x : 0.2f * x; }

// ---------------- init + edge dtype detect ----------------
__global__ void __launch_bounds__(256) init_kernel(const int* __restrict__ e) {
    int i = blockIdx.x * 256 + threadIdx.x;
    if (i < NN) { g_deg[i] = 0; g_cur[i] = 0; }
    if (i < 64) g_pflag[i] = 0;
    __shared__ int bad;
    if (blockIdx.x == 0) {
        if (threadIdx.x == 0) bad = 0;
        __syncthreads();
        if (e[2 * threadIdx.x + 1] != 0) bad = 1;
        __syncthreads();
        if (threadIdx.x == 0) g_is64 = bad ? 0 : 1;
    }
}

__device__ __forceinline__ int eval_idx(const void* e, long long idx) {
    return g_is64 ? (int)((const long long*)e)[idx] : ((const int*)e)[idx];
}

__global__ void count_kernel(const void* __restrict__ e, int E, int EP) {
    int i = blockIdx.x * blockDim.x + threadIdx.x;
    if (i >= EP) return;
    int d = (i < E) ? eval_idx(e, (long long)E + i) : (i - E);
    atomicAdd(&g_deg[d], 1);
}

// ---------------- single-pass scan with parallel lookback ----------------
__global__ void __launch_bounds__(1024) scan_kernel() {
    __shared__ int sh[1024];
    __shared__ int s_prefix;
    int b = blockIdx.x;
    int t = threadIdx.x;
    int i = b * 1024 + t;
    int v = (i < NN) ? g_deg[i] : 0;
    sh[t] = v;
    __syncthreads();
#pragma unroll
    for (int off = 1; off < 1024; off <<= 1) {
        int tv = (t >= off) ? sh[t - off] : 0;
        __syncthreads();
        sh[t] += tv;
        __syncthreads();
    }
    int total = sh[1023];
    if (t == 1023) {
        __threadfence();
        atomicExch(&g_pflag[b], total + 1);
    }
    if (t < 32) {
        int sum = 0;
        for (int p = t; p < b; p += 32) {
            int w;
            do { w = atomicAdd(&g_pflag[p], 0); } while (w == 0);
            sum += w - 1;
        }
#pragma unroll
        for (int off = 16; off; off >>= 1) sum += __shfl_xor_sync(0xffffffffu, sum, off);
        if (t == 0) s_prefix = sum;
    }
    __syncthreads();
    int prefix = s_prefix;
    if (i < NN) g_rowptr[i] = prefix + sh[t] - v;
    if (b == (int)gridDim.x - 1 && t == 1023) g_rowptr[NN] = prefix + total;
}

__global__ void scatter_kernel(const void* __restrict__ e, int E, int EP) {
    int i = blockIdx.x * blockDim.x + threadIdx.x;
    if (i >= EP) return;
    int s, d;
    if (i < E) { s = eval_idx(e, i); d = eval_idx(e, (long long)E + i); }
    else       { s = i - E; d = s; }
    int pos = atomicAdd(&g_cur[d], 1);
    g_col[g_rowptr[d] + pos] = s;
}

// ---------------- fp16 MMA helper ----------------
__device__ __forceinline__ void mma_f16(
    float* c, unsigned int a0, unsigned int a1, unsigned int a2, unsigned int a3,
    unsigned int b0, unsigned int b1)
{
    asm("mma.sync.aligned.m16n8k16.row.col.f32.f16.f16.f32 "
        "{%0,%1,%2,%3}, {%4,%5,%6,%7}, {%8,%9}, {%0,%1,%2,%3};"
        : "+f"(c[0]), "+f"(c[1]), "+f"(c[2]), "+f"(c[3])
        : "r"(a0), "r"(a1), "r"(a2), "r"(a3), "r"(b0), "r"(b1));
}

// ---------------- GEMM (fp16 HMMA, fp32 accum) + fused s/d projections ------
// C[M,Nc] = A[M,K] @ B[K,Nc]; A fp32 (a_half=0) or fp16 (a_half=1), B fp32.
// Writes fp16 Ch; epilogue computes per-node per-head s/d projections.
// 128x128 block tile, 8 warps (2x4), warp tile 64x32, BK=16.
__global__ void __launch_bounds__(256) gemm_kernel(
    const void* __restrict__ Araw, const float* __restrict__ B,
    __half* __restrict__ Ch,
    const float* __restrict__ as, const float* __restrict__ ad,
    float* __restrict__ sOut, float* __restrict__ dOut,
    int M, int K, int Nc, int cpl2, int a_half)
{
    __shared__ __half As[128][24];    // row-major m x k, stride 24 halves (48B)
    __shared__ __half Bs[16][136];    // k-major k x n, stride 136 halves (272B)
    __shared__ float sm_s[128][4];
    __shared__ float sm_d[128][4];
    int tid = threadIdx.x;
    int lane = tid & 31;
    int w = tid >> 5;
    int wm = (w & 1) * 64;
    int wn = (w >> 1) * 32;
    int lr = lane >> 2;   // 0..7
    int lc = lane & 3;    // 0..3
    int row0 = blockIdx.y * 128;
    int col0 = blockIdx.x * 128;

    for (int q = tid; q < 512; q += 256) {
        ((float*)sm_s)[q] = 0.f;
        ((float*)sm_d)[q] = 0.f;
    }

    float c[4][4][4];
#pragma unroll
    for (int i = 0; i < 4; i++)
#pragma unroll
        for (int j = 0; j < 4; j++)
#pragma unroll
            for (int r = 0; r < 4; r++) c[i][j][r] = 0.f;

    const float* Af = (const float*)Araw;
    const __half* Ah = (const __half*)Araw;

    for (int k0 = 0; k0 < K; k0 += 16) {
        if (k0) __syncthreads();
        // stage A
        if (a_half) {
            int r = tid >> 1;
            int ko = (tid & 1) * 8;
            int gr = row0 + r;
            uint4 v = make_uint4(0u, 0u, 0u, 0u);
            if (gr < M) v = *(const uint4*)(Ah + (long long)gr * K + k0 + ko);
            *(uint4*)&As[r][ko] = v;     // 48B row stride: 16B-aligned
        } else {
#pragma unroll
            for (int s0 = 0; s0 < 2; s0++) {
                int slot = tid + s0 * 256;
                int r = slot >> 2;
                int kk = (slot & 3) << 2;
                float4 v = make_float4(0.f, 0.f, 0.f, 0.f);
                int gr = row0 + r;
                if (gr < M) v = *(const float4*)(Af + (long long)gr * K + k0 + kk);
                __half2 h0 = __float22half2_rn(make_float2(v.x, v.y));
                __half2 h1 = __float22half2_rn(make_float2(v.z, v.w));
                *(__half2*)&As[r][kk]     = h0;
                *(__half2*)&As[r][kk + 2] = h1;
            }
        }
        // stage B (fp32 -> fp16)
#pragma unroll
        for (int s0 = 0; s0 < 2; s0++) {
            int slot = tid + s0 * 256;
            int kk = slot >> 5;
            int cc = (slot & 31) << 2;
            float4 v = *(const float4*)(B + (long long)(k0 + kk) * Nc + col0 + cc);
            __half2 h0 = __float22half2_rn(make_float2(v.x, v.y));
            __half2 h1 = __float22half2_rn(make_float2(v.z, v.w));
            *(__half2*)&Bs[kk][cc]     = h0;
            *(__half2*)&Bs[kk][cc + 2] = h1;
        }
        __syncthreads();

        // B fragments: b0 = {B[2lc][n], B[2lc+1][n]}, b1 = k+8; n = wn+nf*8+lr
        unsigned int bf[4][2];
#pragma unroll
        for (int nf = 0; nf < 4; nf++) {
            int n = wn + nf * 8 + lr;
            __half2 b0 = __halves2half2(Bs[2 * lc][n],     Bs[2 * lc + 1][n]);
            __half2 b1 = __halves2half2(Bs[2 * lc + 8][n], Bs[2 * lc + 9][n]);
            bf[nf][0] = *(unsigned int*)&b0;
            bf[nf][1] = *(unsigned int*)&b1;
        }
#pragma unroll
        for (int mf = 0; mf < 4; mf++) {
            int r = wm + mf * 16 + lr;
            unsigned int a0 = *(unsigned int*)&As[r][2 * lc];
            unsigned int a1 = *(unsigned int*)&As[r + 8][2 * lc];
            unsigned int a2 = *(unsigned int*)&As[r][2 * lc + 8];
            unsigned int a3 = *(unsigned int*)&As[r + 8][2 * lc + 8];
#pragma unroll
            for (int nf = 0; nf < 4; nf++)
                mma_f16(c[mf][nf], a0, a1, a2, a3, bf[nf][0], bf[nf][1]);
        }
    }

    // ---- epilogue: fp16 store + fused s/d (one head per warp n-tile) ----
    int hlw = wn >> cpl2;
    float av[4][2], dv[4][2];
#pragma unroll
    for (int nf = 0; nf < 4; nf++) {
#pragma unroll
        for (int e = 0; e < 2; e++) {
            int cg = col0 + wn + nf * 8 + lc * 2 + e;
            av[nf][e] = as[cg];
            dv[nf][e] = ad[cg];
        }
    }
#pragma unroll
    for (int mf = 0; mf < 4; mf++) {
#pragma unroll
        for (int rs = 0; rs < 2; rs++) {
            int row = wm + mf * 16 + lr + rs * 8;
            int gr = row0 + row;
            if (gr < M) {
                float ps = 0.f, pd = 0.f;
#pragma unroll
                for (int nf = 0; nf < 4; nf++) {
                    float o0 = c[mf][nf][rs * 2 + 0];
                    float o1 = c[mf][nf][rs * 2 + 1];
                    ps += o0 * av[nf][0] + o1 * av[nf][1];
                    pd += o0 * dv[nf][0] + o1 * dv[nf][1];
                    __half2 hp = __float22half2_rn(make_float2(o0, o1));
                    *(__half2*)(Ch + (long long)gr * Nc + col0 + wn + nf * 8 + lc * 2) = hp;
                }
                atomicAdd(&sm_s[row][hlw], ps);
                atomicAdd(&sm_d[row][hlw], pd);
            }
        }
    }
    __syncthreads();
    int hpb = 128 >> cpl2;
    int hb  = col0 >> cpl2;
    for (int q = tid; q < 128 * hpb; q += 256) {
        int r = q / hpb, hh = q % hpb;
        int gr = row0 + r;
        if (gr < M) {
            sOut[4 * gr + hb + hh] = sm_s[r][hh];
            dOut[4 * gr + hb + hh] = sm_d[r][hh];
        }
    }
}

__device__ __forceinline__ void acc8_fp16(float* acc, uint4 v, float ex) {
    float2 f0 = __half22float2(*(__half2*)&v.x);
    float2 f1 = __half22float2(*(__half2*)&v.y);
    float2 f2 = __half22float2(*(__half2*)&v.z);
    float2 f3 = __half22float2(*(__half2*)&v.w);
    acc[0] += ex * f0.x; acc[1] += ex * f0.y;
    acc[2] += ex * f1.x; acc[3] += ex * f1.y;
    acc[4] += ex * f2.x; acc[5] += ex * f2.y;
    acc[6] += ex * f3.x; acc[7] += ex * f3.y;
}

// ---------------- GAT aggregation layer 1 (fp16 gather, fused BN+ELU) --------
// Writes out1 as fp16 (feeds gemm2).
__global__ void __launch_bounds__(256) agg1_kernel(
    const float* __restrict__ b1, const float* __restrict__ gm,
    const float* __restrict__ bt, const float* __restrict__ mn,
    const float* __restrict__ vr)
{
    int gw = (blockIdx.x * blockDim.x + threadIdx.x) >> 5;
    if (gw >= NN) return;
    int l = threadIdx.x & 31;
    int start = g_rowptr[gw], end = g_rowptr[gw + 1];
    int head = l >> 3;
    float dh = g_d1[4 * gw + head];
    int c0 = l << 3;
    float acc[8] = {0.f, 0.f, 0.f, 0.f, 0.f, 0.f, 0.f, 0.f};
    float den = 0.f;

    int j = start;
    for (; j + 4 <= end; j += 4) {
        int s0 = g_col[j], s1 = g_col[j + 1], s2 = g_col[j + 2], s3 = g_col[j + 3];
        float e0 = __expf(lrelu(g_s1[4 * s0 + head] + dh));
        float e1 = __expf(lrelu(g_s1[4 * s1 + head] + dh));
        float e2 = __expf(lrelu(g_s1[4 * s2 + head] + dh));
        float e3 = __expf(lrelu(g_s1[4 * s3 + head] + dh));
        uint4 v0 = *(const uint4*)(g_h1h + (long long)s0 * 256 + c0);
        uint4 v1 = *(const uint4*)(g_h1h + (long long)s1 * 256 + c0);
        uint4 v2 = *(const uint4*)(g_h1h + (long long)s2 * 256 + c0);
        uint4 v3 = *(const uint4*)(g_h1h + (long long)s3 * 256 + c0);
        den += (e0 + e1) + (e2 + e3);
        acc8_fp16(acc, v0, e0);
        acc8_fp16(acc, v1, e1);
        acc8_fp16(acc, v2, e2);
        acc8_fp16(acc, v3, e3);
    }
    for (; j < end; j++) {
        int s = g_col[j];
        float ex = __expf(lrelu(g_s1[4 * s + head] + dh));
        den += ex;
        uint4 v = *(const uint4*)(g_h1h + (long long)s * 256 + c0);
        acc8_fp16(acc, v, ex);
    }
    float inv = 1.f / (den + 1e-16f);
    float out[8];
#pragma unroll
    for (int i = 0; i < 8; i++) {
        int cc = c0 + i;
        float v = acc[i] * inv + b1[cc];
        v = (v - mn[cc]) * rsqrtf(vr[cc] + EPS_BN) * gm[cc] + bt[cc];
        out[i] = v > 0.f ? v : expm1f(v);
    }
    __half2 q0 = __float22half2_rn(make_float2(out[0], out[1]));
    __half2 q1 = __float22half2_rn(make_float2(out[2], out[3]));
    __half2 q2 = __float22half2_rn(make_float2(out[4], out[5]));
    __half2 q3 = __float22half2_rn(make_float2(out[6], out[7]));
    uint4 wv;
    wv.x = *(unsigned int*)&q0; wv.y = *(unsigned int*)&q1;
    wv.z = *(unsigned int*)&q2; wv.w = *(unsigned int*)&q3;
    *(uint4*)(g_out1h + (long long)gw * 256 + c0) = wv;
}

// ------------ GAT aggregation layer 2 (fp16 gather, BN+ELU+FC head) ----------
__global__ void __launch_bounds__(256) agg2_kernel(
    const float* __restrict__ b2, const float* __restrict__ gm,
    const float* __restrict__ bt, const float* __restrict__ mn,
    const float* __restrict__ vr, const float* __restrict__ fcW,
    const float* __restrict__ fcb, float* __restrict__ out)
{
    int gw = (blockIdx.x * blockDim.x + threadIdx.x) >> 5;
    if (gw >= NN) return;
    int l = threadIdx.x & 31;
    int start = g_rowptr[gw], end = g_rowptr[gw + 1];
    int head = l >> 3;
    float dh = g_d2[4 * gw + head];
    int c0 = l << 2;
    float acc[4] = {0.f, 0.f, 0.f, 0.f};
    float den = 0.f;

    int j = start;
    for (; j + 4 <= end; j += 4) {
        int s0 = g_col[j], s1 = g_col[j + 1], s2 = g_col[j + 2], s3 = g_col[j + 3];
        float e0 = __expf(lrelu(g_s2[4 * s0 + head] + dh));
        float e1 = __expf(lrelu(g_s2[4 * s1 + head] + dh));
        float e2 = __expf(lrelu(g_s2[4 * s2 + head] + dh));
        float e3 = __expf(lrelu(g_s2[4 * s3 + head] + dh));
        uint2 v0 = *(const uint2*)(g_h2h + (long long)s0 * 128 + c0);
        uint2 v1 = *(const uint2*)(g_h2h + (long long)s1 * 128 + c0);
        uint2 v2 = *(const uint2*)(g_h2h + (long long)s2 * 128 + c0);
        uint2 v3 = *(const uint2*)(g_h2h + (long long)s3 * 128 + c0);
        den += (e0 + e1) + (e2 + e3);
        float2 f;
        f = __half22float2(*(__half2*)&v0.x); acc[0] += e0*f.x; acc[1] += e0*f.y;
        f = __half22float2(*(__half2*)&v0.y); acc[2] += e0*f.x; acc[3] += e0*f.y;
        f = __half22float2(*(__half2*)&v1.x); acc[0] += e1*f.x; acc[1] += e1*f.y;
        f = __half22float2(*(__half2*)&v1.y); acc[2] += e1*f.x; acc[3] += e1*f.y;
        f = __half22float2(*(__half2*)&v2.x); acc[0] += e2*f.x; acc[1] += e2*f.y;
        f = __half22float2(*(__half2*)&v2.y); acc[2] += e2*f.x; acc[3] += e2*f.y;
        f = __half22float2(*(__half2*)&v3.x); acc[0] += e3*f.x; acc[1] += e3*f.y;
        f = __half22float2(*(__half2*)&v3.y); acc[2] += e3*f.x; acc[3] += e3*f.y;
    }
    for (; j < end; j++) {
        int s = g_col[j];
        float ex = __expf(lrelu(g_s2[4 * s + head] + dh));
        den += ex;
        uint2 v0 = *(const uint2*)(g_h2h + (long long)s * 128 + c0);
        float2 f;
        f = __half22float2(*(__half2*)&v0.x); acc[0] += ex*f.x; acc[1] += ex*f.y;
        f = __half22float2(*(__half2*)&v0.y); acc[2] += ex*f.x; acc[3] += ex*f.y;
    }
    float inv = 1.f / (den + 1e-16f);
    float r = 0.f;
#pragma unroll
    for (int i = 0; i < 4; i++) {
        int cc = c0 + i;
        float v = acc[i] * inv + b2[cc];
        v = (v - mn[cc]) * rsqrtf(vr[cc] + EPS_BN) * gm[cc] + bt[cc];
        v = v > 0.f ? v : expm1f(v);
        r += v * fcW[cc];
    }
#pragma unroll
    for (int off = 16; off; off >>= 1) r += __shfl_xor_sync(0xffffffffu, r, off);
    if (l == 0) out[gw] = r + fcb[0];
}

// ---------------- launch ----------------
extern "C" void kernel_launch(void* const* d_in, const int* in_sizes, int n_in,
                              void* d_out, int out_size) {
    const float* x    = (const float*)d_in[0];
    const void*  eidx = d_in[1];
    const float* W1   = (const float*)d_in[2];
    const float* a1s  = (const float*)d_in[3];
    const float* a1d  = (const float*)d_in[4];
    const float* b1   = (const float*)d_in[5];
    const float* g1   = (const float*)d_in[6];
    const float* be1  = (const float*)d_in[7];
    const float* m1   = (const float*)d_in[8];
    const float* v1   = (const float*)d_in[9];
    const float* W2   = (const float*)d_in[10];
    const float* a2s  = (const float*)d_in[11];
    const float* a2d  = (const float*)d_in[12];
    const float* b2   = (const float*)d_in[13];
    const float* g2   = (const float*)d_in[14];
    const float* be2  = (const float*)d_in[15];
    const float* m2   = (const float*)d_in[16];
    const float* v2   = (const float*)d_in[17];
    const float* fcW  = (const float*)d_in[18];
    const float* fcb  = (const float*)d_in[19];

    int E  = in_sizes[1] / 2;
    int EP = E + NN;

    float *s1p, *d1p, *s2p, *d2p;
    __half *h1hp, *h2hp, *out1hp;
    cudaGetSymbolAddress((void**)&h1hp,   g_h1h);
    cudaGetSymbolAddress((void**)&h2hp,   g_h2h);
    cudaGetSymbolAddress((void**)&out1hp, g_out1h);
    cudaGetSymbolAddress((void**)&s1p,    g_s1);
    cudaGetSymbolAddress((void**)&d1p,    g_d1);
    cudaGetSymbolAddress((void**)&s2p,    g_s2);
    cudaGetSymbolAddress((void**)&d2p,    g_d2);

    const int TPB = 256;
    int warp_blocks = (NN * 32 + TPB - 1) / TPB;
    int scan_blocks = (NN + 1023) / 1024;

    init_kernel<<<(NN + 255) / 256, 256>>>((const int*)eidx);              // 1
    count_kernel<<<(EP + TPB - 1) / TPB, TPB>>>(eidx, E, EP);              // 2
    scan_kernel<<<scan_blocks, 1024>>>();                                  // 3
    // gemm1 at slot 4 (independent of CSR) -> gets profiled
    gemm_kernel<<<dim3(2, (NN + 127) / 128), 256>>>(                       // 4
        x, W1, h1hp, a1s, a1d, s1p, d1p, NN, 128, 256, 6, 0);
    scatter_kernel<<<(EP + TPB - 1) / TPB, TPB>>>(eidx, E, EP);            // 5
    agg1_kernel<<<warp_blocks, TPB>>>(b1, g1, be1, m1, v1);                // 6
    gemm_kernel<<<dim3(1, (NN + 127) / 128), 256>>>(                       // 7
        out1hp, W2, h2hp, a2s, a2d, s2p, d2p, NN, 256, 128, 5, 1);
    agg2_kernel<<<warp_blocks, TPB>>>(b2, g2, be2, m2, v2, fcW, fcb, (float*)d_out); // 8
}

// round 8
// speedup vs baseline: 1.6447x; 1.0294x over previous
#include <cuda_runtime.h>
#include <cuda_fp16.h>
#include <math.h>

#define NN 50000
#define EPS_BN 1e-5f

// ---------------- scratch (device globals: allocation-free) ----------------
static __device__ __half g_h1h[(long long)NN * 256];   // fp16 h1 for gather
static __device__ __half g_out1h[(long long)NN * 256]; // fp16 elu(bn(gat1)) (gemm2 A)
static __device__ __half g_h2h[(long long)NN * 128];   // fp16 h2 for gather
static __device__ float g_s1[NN * 4];
static __device__ float g_d1[NN * 4];
static __device__ float g_s2[NN * 4];
static __device__ float g_d2[NN * 4];
static __device__ int g_deg[NN];
static __device__ int g_cur[NN];
static __device__ int g_rowptr[NN + 1];
static __device__ int g_pflag[64];
static __device__ int g_col[900000];
static __device__ int g_is64;

__device__ __forceinline__ float lrelu(float x) { return x > 0.f ? x : 0.2f * x; }

// ---------------- init + edge dtype detect ----------------
__global__ void __launch_bounds__(256) init_kernel(const int* __restrict__ e) {
    int i = blockIdx.x * 256 + threadIdx.x;
    if (i < NN) { g_deg[i] = 0; g_cur[i] = 0; }
    if (i < 64) g_pflag[i] = 0;
    __shared__ int bad;
    if (blockIdx.x == 0) {
        if (threadIdx.x == 0) bad = 0;
        __syncthreads();
        if (e[2 * threadIdx.x + 1] != 0) bad = 1;
        __syncthreads();
        if (threadIdx.x == 0) g_is64 = bad ? 0 : 1;
    }
}

__device__ __forceinline__ int eval_idx(const void* e, long long idx) {
    return g_is64 ? (int)((const long long*)e)[idx] : ((const int*)e)[idx];
}

__global__ void count_kernel(const void* __restrict__ e, int E, int EP) {
    int i = blockIdx.x * blockDim.x + threadIdx.x;
    if (i >= EP) return;
    int d = (i < E) ? eval_idx(e, (long long)E + i) : (i - E);
    atomicAdd(&g_deg[d], 1);
}

// ---------------- single-pass scan with parallel lookback ----------------
__global__ void __launch_bounds__(1024) scan_kernel() {
    __shared__ int sh[1024];
    __shared__ int s_prefix;
    int b = blockIdx.x;
    int t = threadIdx.x;
    int i = b * 1024 + t;
    int v = (i < NN) ? g_deg[i] : 0;
    sh[t] = v;
    __syncthreads();
#pragma unroll
    for (int off = 1; off < 1024; off <<= 1) {
        int tv = (t >= off) ? sh[t - off] : 0;
        __syncthreads();
        sh[t] += tv;
        __syncthreads();
    }
    int total = sh[1023];
    if (t == 1023) {
        __threadfence();
        atomicExch(&g_pflag[b], total + 1);
    }
    if (t < 32) {
        int sum = 0;
        for (int p = t; p < b; p += 32) {
            int w;
            do { w = atomicAdd(&g_pflag[p], 0); } while (w == 0);
            sum += w - 1;
        }
#pragma unroll
        for (int off = 16; off; off >>= 1) sum += __shfl_xor_sync(0xffffffffu, sum, off);
        if (t == 0) s_prefix = sum;
    }
    __syncthreads();
    int prefix = s_prefix;
    if (i < NN) g_rowptr[i] = prefix + sh[t] - v;
    if (b == (int)gridDim.x - 1 && t == 1023) g_rowptr[NN] = prefix + total;
}

__global__ void scatter_kernel(const void* __restrict__ e, int E, int EP) {
    int i = blockIdx.x * blockDim.x + threadIdx.x;
    if (i >= EP) return;
    int s, d;
    if (i < E) { s = eval_idx(e, i); d = eval_idx(e, (long long)E + i); }
    else       { s = i - E; d = s; }
    int pos = atomicAdd(&g_cur[d], 1);
    g_col[g_rowptr[d] + pos] = s;
}

// ---------------- MMA / LDSM helpers ----------------
__device__ __forceinline__ void mma_f16(
    float* c, unsigned int a0, unsigned int a1, unsigned int a2, unsigned int a3,
    unsigned int b0, unsigned int b1)
{
    asm("mma.sync.aligned.m16n8k16.row.col.f32.f16.f16.f32 "
        "{%0,%1,%2,%3}, {%4,%5,%6,%7}, {%8,%9}, {%0,%1,%2,%3};"
        : "+f"(c[0]), "+f"(c[1]), "+f"(c[2]), "+f"(c[3])
        : "r"(a0), "r"(a1), "r"(a2), "r"(a3), "r"(b0), "r"(b1));
}

__device__ __forceinline__ void ldsm_x4(
    unsigned int& d0, unsigned int& d1, unsigned int& d2, unsigned int& d3,
    unsigned int addr)
{
    asm volatile("ldmatrix.sync.aligned.m8n8.x4.shared.b16 {%0,%1,%2,%3}, [%4];"
        : "=r"(d0), "=r"(d1), "=r"(d2), "=r"(d3) : "r"(addr));
}

__device__ __forceinline__ void ldsm_x4_trans(
    unsigned int& d0, unsigned int& d1, unsigned int& d2, unsigned int& d3,
    unsigned int addr)
{
    asm volatile("ldmatrix.sync.aligned.m8n8.x4.trans.shared.b16 {%0,%1,%2,%3}, [%4];"
        : "=r"(d0), "=r"(d1), "=r"(d2), "=r"(d3) : "r"(addr));
}

// ---------------- GEMM (fp16 HMMA + ldmatrix) + fused s/d projections -------
// C[M,Nc] = A[M,K] @ B[K,Nc]; A fp32 (a_half=0) or fp16 (a_half=1), B fp32.
// 128x128 block tile, 8 warps (2x4), warp tile 64x32, BK=16.
__global__ void __launch_bounds__(256) gemm_kernel(
    const void* __restrict__ Araw, const float* __restrict__ B,
    __half* __restrict__ Ch,
    const float* __restrict__ as, const float* __restrict__ ad,
    float* __restrict__ sOut, float* __restrict__ dOut,
    int M, int K, int Nc, int cpl2, int a_half)
{
    __shared__ __half As[128][24];    // row-major m x k, stride 48B
    __shared__ __half Bs[16][136];    // k-major k x n, stride 272B
    __shared__ float sm_s[128][4];
    __shared__ float sm_d[128][4];
    int tid = threadIdx.x;
    int lane = tid & 31;
    int w = tid >> 5;
    int wm = (w & 1) * 64;
    int wn = (w >> 1) * 32;
    int lr = lane >> 2;   // 0..7
    int lc = lane & 3;    // 0..3
    int row0 = blockIdx.y * 128;
    int col0 = blockIdx.x * 128;

    for (int q = tid; q < 512; q += 256) {
        ((float*)sm_s)[q] = 0.f;
        ((float*)sm_d)[q] = 0.f;
    }

    // per-lane LDSM addresses (constant across k-iterations)
    unsigned int a_addr[4], b_addr[2];
    {
        int arow = wm + (lane & 15);
        int akoff = (lane >> 4) * 8;
#pragma unroll
        for (int mf = 0; mf < 4; mf++)
            a_addr[mf] = (unsigned int)__cvta_generic_to_shared(&As[arow + mf * 16][akoff]);
        int brow = lane & 15;
#pragma unroll
        for (int np = 0; np < 2; np++) {
            int bn = wn + np * 16 + (lane >> 4) * 8;
            b_addr[np] = (unsigned int)__cvta_generic_to_shared(&Bs[brow][bn]);
        }
    }

    float c[4][4][4];
#pragma unroll
    for (int i = 0; i < 4; i++)
#pragma unroll
        for (int j = 0; j < 4; j++)
#pragma unroll
            for (int r = 0; r < 4; r++) c[i][j][r] = 0.f;

    const float* Af = (const float*)Araw;
    const __half* Ah = (const __half*)Araw;

    for (int k0 = 0; k0 < K; k0 += 16) {
        if (k0) __syncthreads();
        // stage A
        if (a_half) {
            int r = tid >> 1;
            int ko = (tid & 1) * 8;
            int gr = row0 + r;
            uint4 v = make_uint4(0u, 0u, 0u, 0u);
            if (gr < M) v = *(const uint4*)(Ah + (long long)gr * K + k0 + ko);
            *(uint4*)&As[r][ko] = v;
        } else {
#pragma unroll
            for (int s0 = 0; s0 < 2; s0++) {
                int slot = tid + s0 * 256;
                int r = slot >> 2;
                int kk = (slot & 3) << 2;
                float4 v = make_float4(0.f, 0.f, 0.f, 0.f);
                int gr = row0 + r;
                if (gr < M) v = *(const float4*)(Af + (long long)gr * K + k0 + kk);
                __half2 h0 = __float22half2_rn(make_float2(v.x, v.y));
                __half2 h1 = __float22half2_rn(make_float2(v.z, v.w));
                *(__half2*)&As[r][kk]     = h0;
                *(__half2*)&As[r][kk + 2] = h1;
            }
        }
        // stage B (fp32 -> fp16)
#pragma unroll
        for (int s0 = 0; s0 < 2; s0++) {
            int slot = tid + s0 * 256;
            int kk = slot >> 5;
            int cc = (slot & 31) << 2;
            float4 v = *(const float4*)(B + (long long)(k0 + kk) * Nc + col0 + cc);
            __half2 h0 = __float22half2_rn(make_float2(v.x, v.y));
            __half2 h1 = __float22half2_rn(make_float2(v.z, v.w));
            *(__half2*)&Bs[kk][cc]     = h0;
            *(__half2*)&Bs[kk][cc + 2] = h1;
        }
        __syncthreads();

        // fragments via ldmatrix
        unsigned int bf[4][2];
#pragma unroll
        for (int np = 0; np < 2; np++) {
            unsigned int d0, d1, d2, d3;
            ldsm_x4_trans(d0, d1, d2, d3, b_addr[np]);
            bf[2 * np][0] = d0;  bf[2 * np][1] = d1;      // n-frag 2np   (b0,b1)
            bf[2 * np + 1][0] = d2; bf[2 * np + 1][1] = d3; // n-frag 2np+1
        }
#pragma unroll
        for (int mf = 0; mf < 4; mf++) {
            unsigned int a0, a1, a2, a3;
            ldsm_x4(a0, a1, a2, a3, a_addr[mf]);
#pragma unroll
            for (int nf = 0; nf < 4; nf++)
                mma_f16(c[mf][nf], a0, a1, a2, a3, bf[nf][0], bf[nf][1]);
        }
    }

    // ---- epilogue: fp16 store + fused s/d (one head per warp n-tile) ----
    int hlw = wn >> cpl2;
    float av[4][2], dv[4][2];
#pragma unroll
    for (int nf = 0; nf < 4; nf++) {
#pragma unroll
        for (int e = 0; e < 2; e++) {
            int cg = col0 + wn + nf * 8 + lc * 2 + e;
            av[nf][e] = as[cg];
            dv[nf][e] = ad[cg];
        }
    }
#pragma unroll
    for (int mf = 0; mf < 4; mf++) {
#pragma unroll
        for (int rs = 0; rs < 2; rs++) {
            int row = wm + mf * 16 + lr + rs * 8;
            int gr = row0 + row;
            if (gr < M) {
                float ps = 0.f, pd = 0.f;
#pragma unroll
                for (int nf = 0; nf < 4; nf++) {
                    float o0 = c[mf][nf][rs * 2 + 0];
                    float o1 = c[mf][nf][rs * 2 + 1];
                    ps += o0 * av[nf][0] + o1 * av[nf][1];
                    pd += o0 * dv[nf][0] + o1 * dv[nf][1];
                    __half2 hp = __float22half2_rn(make_float2(o0, o1));
                    *(__half2*)(Ch + (long long)gr * Nc + col0 + wn + nf * 8 + lc * 2) = hp;
                }
                atomicAdd(&sm_s[row][hlw], ps);
                atomicAdd(&sm_d[row][hlw], pd);
            }
        }
    }
    __syncthreads();
    int hpb = 128 >> cpl2;
    int hb  = col0 >> cpl2;
    for (int q = tid; q < 128 * hpb; q += 256) {
        int r = q / hpb, hh = q % hpb;
        int gr = row0 + r;
        if (gr < M) {
            sOut[4 * gr + hb + hh] = sm_s[r][hh];
            dOut[4 * gr + hb + hh] = sm_d[r][hh];
        }
    }
}

__device__ __forceinline__ void acc8_fp16(float* acc, uint4 v, float ex) {
    float2 f0 = __half22float2(*(__half2*)&v.x);
    float2 f1 = __half22float2(*(__half2*)&v.y);
    float2 f2 = __half22float2(*(__half2*)&v.z);
    float2 f3 = __half22float2(*(__half2*)&v.w);
    acc[0] += ex * f0.x; acc[1] += ex * f0.y;
    acc[2] += ex * f1.x; acc[3] += ex * f1.y;
    acc[4] += ex * f2.x; acc[5] += ex * f2.y;
    acc[6] += ex * f3.x; acc[7] += ex * f3.y;
}

// ---------------- GAT aggregation layer 1 (fp16 gather, fused BN+ELU) --------
__global__ void __launch_bounds__(256) agg1_kernel(
    const float* __restrict__ b1, const float* __restrict__ gm,
    const float* __restrict__ bt, const float* __restrict__ mn,
    const float* __restrict__ vr)
{
    int gw = (blockIdx.x * blockDim.x + threadIdx.x) >> 5;
    if (gw >= NN) return;
    int l = threadIdx.x & 31;
    int start = g_rowptr[gw], end = g_rowptr[gw + 1];
    int head = l >> 3;
    float dh = g_d1[4 * gw + head];
    int c0 = l << 3;
    float acc[8] = {0.f, 0.f, 0.f, 0.f, 0.f, 0.f, 0.f, 0.f};
    float den = 0.f;

    int j = start;
    for (; j + 4 <= end; j += 4) {
        int s0 = g_col[j], s1 = g_col[j + 1], s2 = g_col[j + 2], s3 = g_col[j + 3];
        float e0 = __expf(lrelu(g_s1[4 * s0 + head] + dh));
        float e1 = __expf(lrelu(g_s1[4 * s1 + head] + dh));
        float e2 = __expf(lrelu(g_s1[4 * s2 + head] + dh));
        float e3 = __expf(lrelu(g_s1[4 * s3 + head] + dh));
        uint4 v0 = *(const uint4*)(g_h1h + (long long)s0 * 256 + c0);
        uint4 v1 = *(const uint4*)(g_h1h + (long long)s1 * 256 + c0);
        uint4 v2 = *(const uint4*)(g_h1h + (long long)s2 * 256 + c0);
        uint4 v3 = *(const uint4*)(g_h1h + (long long)s3 * 256 + c0);
        den += (e0 + e1) + (e2 + e3);
        acc8_fp16(acc, v0, e0);
        acc8_fp16(acc, v1, e1);
        acc8_fp16(acc, v2, e2);
        acc8_fp16(acc, v3, e3);
    }
    for (; j < end; j++) {
        int s = g_col[j];
        float ex = __expf(lrelu(g_s1[4 * s + head] + dh));
        den += ex;
        uint4 v = *(const uint4*)(g_h1h + (long long)s * 256 + c0);
        acc8_fp16(acc, v, ex);
    }
    float inv = 1.f / (den + 1e-16f);
    float out[8];
#pragma unroll
    for (int i = 0; i < 8; i++) {
        int cc = c0 + i;
        float v = acc[i] * inv + b1[cc];
        v = (v - mn[cc]) * rsqrtf(vr[cc] + EPS_BN) * gm[cc] + bt[cc];
        out[i] = v > 0.f ? v : expm1f(v);
    }
    __half2 q0 = __float22half2_rn(make_float2(out[0], out[1]));
    __half2 q1 = __float22half2_rn(make_float2(out[2], out[3]));
    __half2 q2 = __float22half2_rn(make_float2(out[4], out[5]));
    __half2 q3 = __float22half2_rn(make_float2(out[6], out[7]));
    uint4 wv;
    wv.x = *(unsigned int*)&q0; wv.y = *(unsigned int*)&q1;
    wv.z = *(unsigned int*)&q2; wv.w = *(unsigned int*)&q3;
    *(uint4*)(g_out1h + (long long)gw * 256 + c0) = wv;
}

// ------------ GAT aggregation layer 2 (fp16 gather, BN+ELU+FC head) ----------
__global__ void __launch_bounds__(256) agg2_kernel(
    const float* __restrict__ b2, const float* __restrict__ gm,
    const float* __restrict__ bt, const float* __restrict__ mn,
    const float* __restrict__ vr, const float* __restrict__ fcW,
    const float* __restrict__ fcb, float* __restrict__ out)
{
    int gw = (blockIdx.x * blockDim.x + threadIdx.x) >> 5;
    if (gw >= NN) return;
    int l = threadIdx.x & 31;
    int start = g_rowptr[gw], end = g_rowptr[gw + 1];
    int head = l >> 3;
    float dh = g_d2[4 * gw + head];
    int c0 = l << 2;
    float acc[4] = {0.f, 0.f, 0.f, 0.f};
    float den = 0.f;

    int j = start;
    for (; j + 4 <= end; j += 4) {
        int s0 = g_col[j], s1 = g_col[j + 1], s2 = g_col[j + 2], s3 = g_col[j + 3];
        float e0 = __expf(lrelu(g_s2[4 * s0 + head] + dh));
        float e1 = __expf(lrelu(g_s2[4 * s1 + head] + dh));
        float e2 = __expf(lrelu(g_s2[4 * s2 + head] + dh));
        float e3 = __expf(lrelu(g_s2[4 * s3 + head] + dh));
        uint2 v0 = *(const uint2*)(g_h2h + (long long)s0 * 128 + c0);
        uint2 v1 = *(const uint2*)(g_h2h + (long long)s1 * 128 + c0);
        uint2 v2 = *(const uint2*)(g_h2h + (long long)s2 * 128 + c0);
        uint2 v3 = *(const uint2*)(g_h2h + (long long)s3 * 128 + c0);
        den += (e0 + e1) + (e2 + e3);
        float2 f;
        f = __half22float2(*(__half2*)&v0.x); acc[0] += e0*f.x; acc[1] += e0*f.y;
        f = __half22float2(*(__half2*)&v0.y); acc[2] += e0*f.x; acc[3] += e0*f.y;
        f = __half22float2(*(__half2*)&v1.x); acc[0] += e1*f.x; acc[1] += e1*f.y;
        f = __half22float2(*(__half2*)&v1.y); acc[2] += e1*f.x; acc[3] += e1*f.y;
        f = __half22float2(*(__half2*)&v2.x); acc[0] += e2*f.x; acc[1] += e2*f.y;
        f = __half22float2(*(__half2*)&v2.y); acc[2] += e2*f.x; acc[3] += e2*f.y;
        f = __half22float2(*(__half2*)&v3.x); acc[0] += e3*f.x; acc[1] += e3*f.y;
        f = __half22float2(*(__half2*)&v3.y); acc[2] += e3*f.x; acc[3] += e3*f.y;
    }
    for (; j < end; j++) {
        int s = g_col[j];
        float ex = __expf(lrelu(g_s2[4 * s + head] + dh));
        den += ex;
        uint2 v0 = *(const uint2*)(g_h2h + (long long)s * 128 + c0);
        float2 f;
        f = __half22float2(*(__half2*)&v0.x); acc[0] += ex*f.x; acc[1] += ex*f.y;
        f = __half22float2(*(__half2*)&v0.y); acc[2] += ex*f.x; acc[3] += ex*f.y;
    }
    float inv = 1.f / (den + 1e-16f);
    float r = 0.f;
#pragma unroll
    for (int i = 0; i < 4; i++) {
        int cc = c0 + i;
        float v = acc[i] * inv + b2[cc];
        v = (v - mn[cc]) * rsqrtf(vr[cc] + EPS_BN) * gm[cc] + bt[cc];
        v = v > 0.f ? v : expm1f(v);
        r += v * fcW[cc];
    }
#pragma unroll
    for (int off = 16; off; off >>= 1) r += __shfl_xor_sync(0xffffffffu, r, off);
    if (l == 0) out[gw] = r + fcb[0];
}

// ---------------- launch ----------------
extern "C" void kernel_launch(void* const* d_in, const int* in_sizes, int n_in,
                              void* d_out, int out_size) {
    const float* x    = (const float*)d_in[0];
    const void*  eidx = d_in[1];
    const float* W1   = (const float*)d_in[2];
    const float* a1s  = (const float*)d_in[3];
    const float* a1d  = (const float*)d_in[4];
    const float* b1   = (const float*)d_in[5];
    const float* g1   = (const float*)d_in[6];
    const float* be1  = (const float*)d_in[7];
    const float* m1   = (const float*)d_in[8];
    const float* v1   = (const float*)d_in[9];
    const float* W2   = (const float*)d_in[10];
    const float* a2s  = (const float*)d_in[11];
    const float* a2d  = (const float*)d_in[12];
    const float* b2   = (const float*)d_in[13];
    const float* g2   = (const float*)d_in[14];
    const float* be2  = (const float*)d_in[15];
    const float* m2   = (const float*)d_in[16];
    const float* v2   = (const float*)d_in[17];
    const float* fcW  = (const float*)d_in[18];
    const float* fcb  = (const float*)d_in[19];

    int E  = in_sizes[1] / 2;
    int EP = E + NN;

    float *s1p, *d1p, *s2p, *d2p;
    __half *h1hp, *h2hp, *out1hp;
    cudaGetSymbolAddress((void**)&h1hp,   g_h1h);
    cudaGetSymbolAddress((void**)&h2hp,   g_h2h);
    cudaGetSymbolAddress((void**)&out1hp, g_out1h);
    cudaGetSymbolAddress((void**)&s1p,    g_s1);
    cudaGetSymbolAddress((void**)&d1p,    g_d1);
    cudaGetSymbolAddress((void**)&s2p,    g_s2);
    cudaGetSymbolAddress((void**)&d2p,    g_d2);

    const int TPB = 256;
    int warp_blocks = (NN * 32 + TPB - 1) / TPB;
    int scan_blocks = (NN + 1023) / 1024;

    init_kernel<<<(NN + 255) / 256, 256>>>((const int*)eidx);              // 1
    count_kernel<<<(EP + TPB - 1) / TPB, TPB>>>(eidx, E, EP);              // 2
    scan_kernel<<<scan_blocks, 1024>>>();                                  // 3
    gemm_kernel<<<dim3(2, (NN + 127) / 128), 256>>>(                       // 4 <- profiled
        x, W1, h1hp, a1s, a1d, s1p, d1p, NN, 128, 256, 6, 0);
    scatter_kernel<<<(EP + TPB - 1) / TPB, TPB>>>(eidx, E, EP);            // 5
    agg1_kernel<<<warp_blocks, TPB>>>(b1, g1, be1, m1, v1);                // 6
    gemm_kernel<<<dim3(1, (NN + 127) / 128), 256>>>(                       // 7
        out1hp, W2, h2hp, a2s, a2d, s2p, d2p, NN, 256, 128, 5, 1);
    agg2_kernel<<<warp_blocks, TPB>>>(b2, g2, be2, m2, v2, fcW, fcb, (float*)d_out); // 8
}

// round 9
// speedup vs baseline: 1.8034x; 1.0965x over previous
#include <cuda_runtime.h>
#include <cuda_fp16.h>
#include <math.h>

#define NN 50000
#define EPS_BN 1e-5f

// ---------------- scratch (device globals: allocation-free) ----------------
static __device__ __half g_xh[(long long)NN * 128];    // fp16 x
static __device__ __half g_w1h[128 * 256];             // fp16 W1
static __device__ __half g_w2h[256 * 128];             // fp16 W2
static __device__ __half g_h1h[(long long)NN * 256];   // fp16 h1 for gather
static __device__ __half g_out1h[(long long)NN * 256]; // fp16 elu(bn(gat1)) (gemm2 A)
static __device__ __half g_h2h[(long long)NN * 128];   // fp16 h2 for gather
static __device__ float g_s1[NN * 4];
static __device__ float g_d1[NN * 4];
static __device__ float g_s2[NN * 4];
static __device__ float g_d2[NN * 4];
static __device__ int g_deg[NN];
static __device__ int g_cur[NN];
static __device__ int g_rowptr[NN + 1];
static __device__ int g_pflag[64];
static __device__ int g_col[900000];
static __device__ int g_is64;

__device__ __forceinline__ float lrelu(float x) { return x > 0.f ? x : 0.2f * x; }

// ---------------- fp32 -> fp16 bulk convert ----------------
__global__ void __launch_bounds__(256) f2h_kernel(
    const float* __restrict__ src, __half* __restrict__ dst, int n4)
{
    int i = blockIdx.x * 256 + threadIdx.x;
    if (i < n4) {
        float4 v = ((const float4*)src)[i];
        __half2 h0 = __float22half2_rn(make_float2(v.x, v.y));
        __half2 h1 = __float22half2_rn(make_float2(v.z, v.w));
        uint2 w;
        w.x = *(unsigned int*)&h0; w.y = *(unsigned int*)&h1;
        ((uint2*)dst)[i] = w;
    }
}

// ---------------- init + edge dtype detect ----------------
__global__ void __launch_bounds__(256) init_kernel(const int* __restrict__ e) {
    int i = blockIdx.x * 256 + threadIdx.x;
    if (i < NN) { g_deg[i] = 0; g_cur[i] = 0; }
    if (i < 64) g_pflag[i] = 0;
    __shared__ int bad;
    if (blockIdx.x == 0) {
        if (threadIdx.x == 0) bad = 0;
        __syncthreads();
        if (e[2 * threadIdx.x + 1] != 0) bad = 1;
        __syncthreads();
        if (threadIdx.x == 0) g_is64 = bad ? 0 : 1;
    }
}

__device__ __forceinline__ int eval_idx(const void* e, long long idx) {
    return g_is64 ? (int)((const long long*)e)[idx] : ((const int*)e)[idx];
}

__global__ void count_kernel(const void* __restrict__ e, int E, int EP) {
    int i = blockIdx.x * blockDim.x + threadIdx.x;
    if (i >= EP) return;
    int d = (i < E) ? eval_idx(e, (long long)E + i) : (i - E);
    atomicAdd(&g_deg[d], 1);
}

// ---------------- single-pass scan with parallel lookback ----------------
__global__ void __launch_bounds__(1024) scan_kernel() {
    __shared__ int sh[1024];
    __shared__ int s_prefix;
    int b = blockIdx.x;
    int t = threadIdx.x;
    int i = b * 1024 + t;
    int v = (i < NN) ? g_deg[i] : 0;
    sh[t] = v;
    __syncthreads();
#pragma unroll
    for (int off = 1; off < 1024; off <<= 1) {
        int tv = (t >= off) ? sh[t - off] : 0;
        __syncthreads();
        sh[t] += tv;
        __syncthreads();
    }
    int total = sh[1023];
    if (t == 1023) {
        __threadfence();
        atomicExch(&g_pflag[b], total + 1);
    }
    if (t < 32) {
        int sum = 0;
        for (int p = t; p < b; p += 32) {
            int w;
            do { w = atomicAdd(&g_pflag[p], 0); } while (w == 0);
            sum += w - 1;
        }
#pragma unroll
        for (int off = 16; off; off >>= 1) sum += __shfl_xor_sync(0xffffffffu, sum, off);
        if (t == 0) s_prefix = sum;
    }
    __syncthreads();
    int prefix = s_prefix;
    if (i < NN) g_rowptr[i] = prefix + sh[t] - v;
    if (b == (int)gridDim.x - 1 && t == 1023) g_rowptr[NN] = prefix + total;
}

__global__ void scatter_kernel(const void* __restrict__ e, int E, int EP) {
    int i = blockIdx.x * blockDim.x + threadIdx.x;
    if (i >= EP) return;
    int s, d;
    if (i < E) { s = eval_idx(e, i); d = eval_idx(e, (long long)E + i); }
    else       { s = i - E; d = s; }
    int pos = atomicAdd(&g_cur[d], 1);
    g_col[g_rowptr[d] + pos] = s;
}

// ---------------- MMA / LDSM / cp.async helpers ----------------
__device__ __forceinline__ void mma_f16(
    float* c, unsigned int a0, unsigned int a1, unsigned int a2, unsigned int a3,
    unsigned int b0, unsigned int b1)
{
    asm("mma.sync.aligned.m16n8k16.row.col.f32.f16.f16.f32 "
        "{%0,%1,%2,%3}, {%4,%5,%6,%7}, {%8,%9}, {%0,%1,%2,%3};"
        : "+f"(c[0]), "+f"(c[1]), "+f"(c[2]), "+f"(c[3])
        : "r"(a0), "r"(a1), "r"(a2), "r"(a3), "r"(b0), "r"(b1));
}

__device__ __forceinline__ void ldsm_x4(
    unsigned int& d0, unsigned int& d1, unsigned int& d2, unsigned int& d3,
    unsigned int addr)
{
    asm volatile("ldmatrix.sync.aligned.m8n8.x4.shared.b16 {%0,%1,%2,%3}, [%4];"
        : "=r"(d0), "=r"(d1), "=r"(d2), "=r"(d3) : "r"(addr));
}

__device__ __forceinline__ void ldsm_x4_trans(
    unsigned int& d0, unsigned int& d1, unsigned int& d2, unsigned int& d3,
    unsigned int addr)
{
    asm volatile("ldmatrix.sync.aligned.m8n8.x4.trans.shared.b16 {%0,%1,%2,%3}, [%4];"
        : "=r"(d0), "=r"(d1), "=r"(d2), "=r"(d3) : "r"(addr));
}

__device__ __forceinline__ void cp_async16(unsigned int dst, const void* src) {
    asm volatile("cp.async.cg.shared.global [%0], [%1], 16;" :: "r"(dst), "l"(src));
}

// ---------------- GEMM (fp16 HMMA, cp.async double-buffered) ----------------
// C[M,Nc] = A[M,K] @ B[K,Nc], all fp16 in / fp32 accum, fp16 out + fused s/d.
// 128x128 block tile, 8 warps (2x4), warp tile 64x32, BK=32, 2-stage pipeline.
__global__ void __launch_bounds__(256) gemm_kernel(
    const __half* __restrict__ A, const __half* __restrict__ B,
    __half* __restrict__ Ch,
    const float* __restrict__ as, const float* __restrict__ ad,
    float* __restrict__ sOut, float* __restrict__ dOut,
    int M, int K, int Nc, int cpl2)
{
    __shared__ __half As[2][128][40];   // 80B row stride (conflict-free LDSM)
    __shared__ __half Bs[2][32][136];   // 272B row stride
    __shared__ float sm_s[128][4];
    __shared__ float sm_d[128][4];
    int tid = threadIdx.x;
    int lane = tid & 31;
    int w = tid >> 5;
    int wm = (w & 1) * 64;
    int wn = (w >> 1) * 32;
    int lr = lane >> 2;
    int lc = lane & 3;
    int row0 = blockIdx.y * 128;
    int col0 = blockIdx.x * 128;

    for (int q = tid; q < 512; q += 256) {
        ((float*)sm_s)[q] = 0.f;
        ((float*)sm_d)[q] = 0.f;
    }

    float c[4][4][4];
#pragma unroll
    for (int i = 0; i < 4; i++)
#pragma unroll
        for (int j = 0; j < 4; j++)
#pragma unroll
            for (int r = 0; r < 4; r++) c[i][j][r] = 0.f;

    // stage chunk k0 into buffer b
    auto stage = [&](int k0, int b) {
#pragma unroll
        for (int s0 = 0; s0 < 2; s0++) {
            int cidx = tid + s0 * 256;
            int r = cidx >> 2;
            int ko = (cidx & 3) << 3;
            long long gr = row0 + r;
            if (gr >= M) gr = M - 1;
            cp_async16((unsigned int)__cvta_generic_to_shared(&As[b][r][ko]),
                       A + gr * K + k0 + ko);
        }
#pragma unroll
        for (int s0 = 0; s0 < 2; s0++) {
            int cidx = tid + s0 * 256;
            int kr = cidx >> 4;
            int no = (cidx & 15) << 3;
            cp_async16((unsigned int)__cvta_generic_to_shared(&Bs[b][kr][no]),
                       B + (long long)(k0 + kr) * Nc + col0 + no);
        }
        asm volatile("cp.async.commit_group;");
    };

    int nchunk = K >> 5;
    stage(0, 0);

    for (int ch = 0; ch < nchunk; ch++) {
        int buf = ch & 1;
        if (ch + 1 < nchunk) {
            stage((ch + 1) << 5, buf ^ 1);
            asm volatile("cp.async.wait_group 1;" ::: "memory");
        } else {
            asm volatile("cp.async.wait_group 0;" ::: "memory");
        }
        __syncthreads();

#pragma unroll
        for (int ks2 = 0; ks2 < 2; ks2++) {
            int ks = ks2 * 16;
            unsigned int bf[4][2];
#pragma unroll
            for (int np = 0; np < 2; np++) {
                int bn = wn + np * 16 + (lane >> 4) * 8;
                unsigned int addr = (unsigned int)__cvta_generic_to_shared(
                    &Bs[buf][(lane & 15) + ks][bn]);
                unsigned int d0, d1, d2, d3;
                ldsm_x4_trans(d0, d1, d2, d3, addr);
                bf[2 * np][0] = d0;     bf[2 * np][1] = d1;
                bf[2 * np + 1][0] = d2; bf[2 * np + 1][1] = d3;
            }
#pragma unroll
            for (int mf = 0; mf < 4; mf++) {
                int arow = wm + (lane & 15) + mf * 16;
                int akoff = (lane >> 4) * 8 + ks;
                unsigned int addr = (unsigned int)__cvta_generic_to_shared(
                    &As[buf][arow][akoff]);
                unsigned int a0, a1, a2, a3;
                ldsm_x4(a0, a1, a2, a3, addr);
#pragma unroll
                for (int nf = 0; nf < 4; nf++)
                    mma_f16(c[mf][nf], a0, a1, a2, a3, bf[nf][0], bf[nf][1]);
            }
        }
        __syncthreads();
    }

    // ---- epilogue: fp16 store + fused s/d (one head per warp n-tile) ----
    int hlw = wn >> cpl2;
    float av[4][2], dv[4][2];
#pragma unroll
    for (int nf = 0; nf < 4; nf++) {
#pragma unroll
        for (int e = 0; e < 2; e++) {
            int cg = col0 + wn + nf * 8 + lc * 2 + e;
            av[nf][e] = as[cg];
            dv[nf][e] = ad[cg];
        }
    }
#pragma unroll
    for (int mf = 0; mf < 4; mf++) {
#pragma unroll
        for (int rs = 0; rs < 2; rs++) {
            int row = wm + mf * 16 + lr + rs * 8;
            int gr = row0 + row;
            if (gr < M) {
                float ps = 0.f, pd = 0.f;
#pragma unroll
                for (int nf = 0; nf < 4; nf++) {
                    float o0 = c[mf][nf][rs * 2 + 0];
                    float o1 = c[mf][nf][rs * 2 + 1];
                    ps += o0 * av[nf][0] + o1 * av[nf][1];
                    pd += o0 * dv[nf][0] + o1 * dv[nf][1];
                    __half2 hp = __float22half2_rn(make_float2(o0, o1));
                    *(__half2*)(Ch + (long long)gr * Nc + col0 + wn + nf * 8 + lc * 2) = hp;
                }
                atomicAdd(&sm_s[row][hlw], ps);
                atomicAdd(&sm_d[row][hlw], pd);
            }
        }
    }
    __syncthreads();
    int hpb = 128 >> cpl2;
    int hb  = col0 >> cpl2;
    for (int q = tid; q < 128 * hpb; q += 256) {
        int r = q / hpb, hh = q % hpb;
        int gr = row0 + r;
        if (gr < M) {
            sOut[4 * gr + hb + hh] = sm_s[r][hh];
            dOut[4 * gr + hb + hh] = sm_d[r][hh];
        }
    }
}

__device__ __forceinline__ void acc8_fp16(float* acc, uint4 v, float ex) {
    float2 f0 = __half22float2(*(__half2*)&v.x);
    float2 f1 = __half22float2(*(__half2*)&v.y);
    float2 f2 = __half22float2(*(__half2*)&v.z);
    float2 f3 = __half22float2(*(__half2*)&v.w);
    acc[0] += ex * f0.x; acc[1] += ex * f0.y;
    acc[2] += ex * f1.x; acc[3] += ex * f1.y;
    acc[4] += ex * f2.x; acc[5] += ex * f2.y;
    acc[6] += ex * f3.x; acc[7] += ex * f3.y;
}

// ---------------- GAT aggregation layer 1 (fp16 gather, fused BN+ELU) --------
__global__ void __launch_bounds__(256) agg1_kernel(
    const float* __restrict__ b1, const float* __restrict__ gm,
    const float* __restrict__ bt, const float* __restrict__ mn,
    const float* __restrict__ vr)
{
    int gw = (blockIdx.x * blockDim.x + threadIdx.x) >> 5;
    if (gw >= NN) return;
    int l = threadIdx.x & 31;
    int start = g_rowptr[gw], end = g_rowptr[gw + 1];
    int head = l >> 3;
    float dh = g_d1[4 * gw + head];
    int c0 = l << 3;
    float acc[8] = {0.f, 0.f, 0.f, 0.f, 0.f, 0.f, 0.f, 0.f};
    float den = 0.f;

    int j = start;
    for (; j + 4 <= end; j += 4) {
        int s0 = g_col[j], s1 = g_col[j + 1], s2 = g_col[j + 2], s3 = g_col[j + 3];
        float e0 = __expf(lrelu(g_s1[4 * s0 + head] + dh));
        float e1 = __expf(lrelu(g_s1[4 * s1 + head] + dh));
        float e2 = __expf(lrelu(g_s1[4 * s2 + head] + dh));
        float e3 = __expf(lrelu(g_s1[4 * s3 + head] + dh));
        uint4 v0 = *(const uint4*)(g_h1h + (long long)s0 * 256 + c0);
        uint4 v1 = *(const uint4*)(g_h1h + (long long)s1 * 256 + c0);
        uint4 v2 = *(const uint4*)(g_h1h + (long long)s2 * 256 + c0);
        uint4 v3 = *(const uint4*)(g_h1h + (long long)s3 * 256 + c0);
        den += (e0 + e1) + (e2 + e3);
        acc8_fp16(acc, v0, e0);
        acc8_fp16(acc, v1, e1);
        acc8_fp16(acc, v2, e2);
        acc8_fp16(acc, v3, e3);
    }
    for (; j < end; j++) {
        int s = g_col[j];
        float ex = __expf(lrelu(g_s1[4 * s + head] + dh));
        den += ex;
        uint4 v = *(const uint4*)(g_h1h + (long long)s * 256 + c0);
        acc8_fp16(acc, v, ex);
    }
    float inv = 1.f / (den + 1e-16f);
    float out[8];
#pragma unroll
    for (int i = 0; i < 8; i++) {
        int cc = c0 + i;
        float v = acc[i] * inv + b1[cc];
        v = (v - mn[cc]) * rsqrtf(vr[cc] + EPS_BN) * gm[cc] + bt[cc];
        out[i] = v > 0.f ? v : expm1f(v);
    }
    __half2 q0 = __float22half2_rn(make_float2(out[0], out[1]));
    __half2 q1 = __float22half2_rn(make_float2(out[2], out[3]));
    __half2 q2 = __float22half2_rn(make_float2(out[4], out[5]));
    __half2 q3 = __float22half2_rn(make_float2(out[6], out[7]));
    uint4 wv;
    wv.x = *(unsigned int*)&q0; wv.y = *(unsigned int*)&q1;
    wv.z = *(unsigned int*)&q2; wv.w = *(unsigned int*)&q3;
    *(uint4*)(g_out1h + (long long)gw * 256 + c0) = wv;
}

// ------------ GAT aggregation layer 2 (fp16 gather, BN+ELU+FC head) ----------
__global__ void __launch_bounds__(256) agg2_kernel(
    const float* __restrict__ b2, const float* __restrict__ gm,
    const float* __restrict__ bt, const float* __restrict__ mn,
    const float* __restrict__ vr, const float* __restrict__ fcW,
    const float* __restrict__ fcb, float* __restrict__ out)
{
    int gw = (blockIdx.x * blockDim.x + threadIdx.x) >> 5;
    if (gw >= NN) return;
    int l = threadIdx.x & 31;
    int start = g_rowptr[gw], end = g_rowptr[gw + 1];
    int head = l >> 3;
    float dh = g_d2[4 * gw + head];
    int c0 = l << 2;
    float acc[4] = {0.f, 0.f, 0.f, 0.f};
    float den = 0.f;

    int j = start;
    for (; j + 4 <= end; j += 4) {
        int s0 = g_col[j], s1 = g_col[j + 1], s2 = g_col[j + 2], s3 = g_col[j + 3];
        float e0 = __expf(lrelu(g_s2[4 * s0 + head] + dh));
        float e1 = __expf(lrelu(g_s2[4 * s1 + head] + dh));
        float e2 = __expf(lrelu(g_s2[4 * s2 + head] + dh));
        float e3 = __expf(lrelu(g_s2[4 * s3 + head] + dh));
        uint2 v0 = *(const uint2*)(g_h2h + (long long)s0 * 128 + c0);
        uint2 v1 = *(const uint2*)(g_h2h + (long long)s1 * 128 + c0);
        uint2 v2 = *(const uint2*)(g_h2h + (long long)s2 * 128 + c0);
        uint2 v3 = *(const uint2*)(g_h2h + (long long)s3 * 128 + c0);
        den += (e0 + e1) + (e2 + e3);
        float2 f;
        f = __half22float2(*(__half2*)&v0.x); acc[0] += e0*f.x; acc[1] += e0*f.y;
        f = __half22float2(*(__half2*)&v0.y); acc[2] += e0*f.x; acc[3] += e0*f.y;
        f = __half22float2(*(__half2*)&v1.x); acc[0] += e1*f.x; acc[1] += e1*f.y;
        f = __half22float2(*(__half2*)&v1.y); acc[2] += e1*f.x; acc[3] += e1*f.y;
        f = __half22float2(*(__half2*)&v2.x); acc[0] += e2*f.x; acc[1] += e2*f.y;
        f = __half22float2(*(__half2*)&v2.y); acc[2] += e2*f.x; acc[3] += e2*f.y;
        f = __half22float2(*(__half2*)&v3.x); acc[0] += e3*f.x; acc[1] += e3*f.y;
        f = __half22float2(*(__half2*)&v3.y); acc[2] += e3*f.x; acc[3] += e3*f.y;
    }
    for (; j < end; j++) {
        int s = g_col[j];
        float ex = __expf(lrelu(g_s2[4 * s + head] + dh));
        den += ex;
        uint2 v0 = *(const uint2*)(g_h2h + (long long)s * 128 + c0);
        float2 f;
        f = __half22float2(*(__half2*)&v0.x); acc[0] += ex*f.x; acc[1] += ex*f.y;
        f = __half22float2(*(__half2*)&v0.y); acc[2] += ex*f.x; acc[3] += ex*f.y;
    }
    float inv = 1.f / (den + 1e-16f);
    float r = 0.f;
#pragma unroll
    for (int i = 0; i < 4; i++) {
        int cc = c0 + i;
        float v = acc[i] * inv + b2[cc];
        v = (v - mn[cc]) * rsqrtf(vr[cc] + EPS_BN) * gm[cc] + bt[cc];
        v = v > 0.f ? v : expm1f(v);
        r += v * fcW[cc];
    }
#pragma unroll
    for (int off = 16; off; off >>= 1) r += __shfl_xor_sync(0xffffffffu, r, off);
    if (l == 0) out[gw] = r + fcb[0];
}

// ---------------- launch ----------------
extern "C" void kernel_launch(void* const* d_in, const int* in_sizes, int n_in,
                              void* d_out, int out_size) {
    const float* x    = (const float*)d_in[0];
    const void*  eidx = d_in[1];
    const float* W1   = (const float*)d_in[2];
    const float* a1s  = (const float*)d_in[3];
    const float* a1d  = (const float*)d_in[4];
    const float* b1   = (const float*)d_in[5];
    const float* g1   = (const float*)d_in[6];
    const float* be1  = (const float*)d_in[7];
    const float* m1   = (const float*)d_in[8];
    const float* v1   = (const float*)d_in[9];
    const float* W2   = (const float*)d_in[10];
    const float* a2s  = (const float*)d_in[11];
    const float* a2d  = (const float*)d_in[12];
    const float* b2   = (const float*)d_in[13];
    const float* g2   = (const float*)d_in[14];
    const float* be2  = (const float*)d_in[15];
    const float* m2   = (const float*)d_in[16];
    const float* v2   = (const float*)d_in[17];
    const float* fcW  = (const float*)d_in[18];
    const float* fcb  = (const float*)d_in[19];

    int E  = in_sizes[1] / 2;
    int EP = E + NN;

    float *s1p, *d1p, *s2p, *d2p;
    __half *h1hp, *h2hp, *out1hp, *xhp, *w1hp, *w2hp;
    cudaGetSymbolAddress((void**)&h1hp,   g_h1h);
    cudaGetSymbolAddress((void**)&h2hp,   g_h2h);
    cudaGetSymbolAddress((void**)&out1hp, g_out1h);
    cudaGetSymbolAddress((void**)&xhp,    g_xh);
    cudaGetSymbolAddress((void**)&w1hp,   g_w1h);
    cudaGetSymbolAddress((void**)&w2hp,   g_w2h);
    cudaGetSymbolAddress((void**)&s1p,    g_s1);
    cudaGetSymbolAddress((void**)&d1p,    g_d1);
    cudaGetSymbolAddress((void**)&s2p,    g_s2);
    cudaGetSymbolAddress((void**)&d2p,    g_d2);

    const int TPB = 256;
    int warp_blocks = (NN * 32 + TPB - 1) / TPB;
    int scan_blocks = (NN + 1023) / 1024;

    init_kernel<<<(NN + 255) / 256, 256>>>((const int*)eidx);
    count_kernel<<<(EP + TPB - 1) / TPB, TPB>>>(eidx, E, EP);
    f2h_kernel<<<(NN * 128 / 4 + 255) / 256, 256>>>(x, xhp, NN * 128 / 4);
    f2h_kernel<<<(128 * 256 / 4 + 255) / 256, 256>>>(W1, w1hp, 128 * 256 / 4);
    f2h_kernel<<<(256 * 128 / 4 + 255) / 256, 256>>>(W2, w2hp, 256 * 128 / 4);
    scan_kernel<<<scan_blocks, 1024>>>();
    gemm_kernel<<<dim3(2, (NN + 127) / 128), 256>>>(
        xhp, w1hp, h1hp, a1s, a1d, s1p, d1p, NN, 128, 256, 6);
    scatter_kernel<<<(EP + TPB - 1) / TPB, TPB>>>(eidx, E, EP);
    agg1_kernel<<<warp_blocks, TPB>>>(b1, g1, be1, m1, v1);
    gemm_kernel<<<dim3(1, (NN + 127) / 128), 256>>>(
        out1hp, w2hp, h2hp, a2s, a2d, s2p, d2p, NN, 256, 128, 5);
    agg2_kernel<<<warp_blocks, TPB>>>(b2, g2, be2, m2, v2, fcW, fcb, (float*)d_out);
}